// round 1
// baseline (speedup 1.0000x reference)
#include <cuda_runtime.h>
#include <math.h>

#define B_    4
#define T_    1024
#define C_    2048
#define H_    32
#define KV_   8
#define D_    64
#define M_TOK (B_ * T_)          // 4096 tokens
#define KVDIM (KV_ * D_)         // 512

// ---------------- scratch (device globals; no allocation allowed) ----------
__device__ float g_q[M_TOK * C_];      // 32 MB  [tok, H*D]
__device__ float g_k[M_TOK * KVDIM];   //  8 MB  [tok, KV*D]
__device__ float g_v[M_TOK * KVDIM];   //  8 MB  [tok, KV*D]
__device__ float g_att[M_TOK * C_];    // 32 MB  [tok, H*D]

// ---------------- SGEMM: C[M,N] = A[M,K] @ B[K,N], all row-major -----------
// 128x128 tile, BK=8, 256 threads, 8x8 per-thread register tile.
__global__ void __launch_bounds__(256) sgemm128(const float* __restrict__ A,
                                                const float* __restrict__ B,
                                                float* __restrict__ C,
                                                int M, int N, int K) {
    __shared__ float As[8][128];   // transposed A tile: As[k][m]
    __shared__ float Bs[8][128];   // Bs[k][n]

    const int tid = threadIdx.x;
    const int bm = blockIdx.y * 128;
    const int bn = blockIdx.x * 128;

    const int ty = tid >> 4;       // 0..15 -> rows ty*8..
    const int tx = tid & 15;       // 0..15 -> cols tx*8..

    // A tile load mapping: one float4 per thread (128 rows x 8 cols)
    const int arow = tid >> 1;          // 0..127
    const int acol = (tid & 1) * 4;     // 0 or 4
    // B tile load mapping: one float4 per thread (8 rows x 128 cols)
    const int brow = tid >> 5;          // 0..7
    const int bcol = (tid & 31) * 4;    // 0..124

    float acc[8][8];
#pragma unroll
    for (int i = 0; i < 8; ++i)
#pragma unroll
        for (int j = 0; j < 8; ++j) acc[i][j] = 0.0f;

    for (int kb = 0; kb < K; kb += 8) {
        float4 av = *(const float4*)(A + (size_t)(bm + arow) * K + kb + acol);
        float4 bv = *(const float4*)(B + (size_t)(kb + brow) * N + bn + bcol);
        As[acol + 0][arow] = av.x;
        As[acol + 1][arow] = av.y;
        As[acol + 2][arow] = av.z;
        As[acol + 3][arow] = av.w;
        *(float4*)&Bs[brow][bcol] = bv;
        __syncthreads();

#pragma unroll
        for (int kk = 0; kk < 8; ++kk) {
            float ar[8], br[8];
            *(float4*)&ar[0] = *(const float4*)&As[kk][ty * 8];
            *(float4*)&ar[4] = *(const float4*)&As[kk][ty * 8 + 4];
            *(float4*)&br[0] = *(const float4*)&Bs[kk][tx * 8];
            *(float4*)&br[4] = *(const float4*)&Bs[kk][tx * 8 + 4];
#pragma unroll
            for (int i = 0; i < 8; ++i)
#pragma unroll
                for (int j = 0; j < 8; ++j) acc[i][j] += ar[i] * br[j];
        }
        __syncthreads();
    }

#pragma unroll
    for (int i = 0; i < 8; ++i) {
        int row = bm + ty * 8 + i;
        float4 v0 = make_float4(acc[i][0], acc[i][1], acc[i][2], acc[i][3]);
        float4 v1 = make_float4(acc[i][4], acc[i][5], acc[i][6], acc[i][7]);
        *(float4*)(C + (size_t)row * N + bn + tx * 8)     = v0;
        *(float4*)(C + (size_t)row * N + bn + tx * 8 + 4) = v1;
    }
}

// ---------------- RoPE (interleaved pairs), applied in-place to q and k ----
// q'[2i]   = q[2i]*cos_i - q[2i+1]*sin_i
// q'[2i+1] = q[2i+1]*cos_i + q[2i]*sin_i,  freq_i = t * 10000^(-i/32)
__global__ void rope_kernel(float* __restrict__ q, float* __restrict__ k) {
    const int NH = H_ + KV_;   // 40 heads total (32 q + 8 k)
    int idx = blockIdx.x * blockDim.x + threadIdx.x;
    const int total = M_TOK * NH * (D_ / 2);
    if (idx >= total) return;

    int p   = idx & 31;                 // pair index 0..31
    int hh  = (idx >> 5) % NH;          // head index (q heads then k heads)
    int tok = idx / (32 * NH);          // global token 0..4095
    int tseq = tok & (T_ - 1);          // position within sequence

    float inv = powf(10000.0f, -(float)p / 32.0f);
    float ang = (float)tseq * inv;
    float s, c;
    sincosf(ang, &s, &c);

    float* base = (hh < H_) ? (q + (size_t)tok * C_ + hh * D_)
                            : (k + (size_t)tok * KVDIM + (hh - H_) * D_);
    float e0 = base[2 * p];
    float e1 = base[2 * p + 1];
    base[2 * p]     = e0 * c - e1 * s;
    base[2 * p + 1] = e1 * c + e0 * s;
}

// ---------------- causal flash attention with GQA (rf=4) -------------------
// grid: (T/64, B*H). Per block: 64 q rows, loop K/V tiles of 32 rows.
// Q/K/V/O all in [tok, head*D] row-major layout.
__global__ void __launch_bounds__(256) flash_kernel(const float* __restrict__ Q,
                                                    const float* __restrict__ K,
                                                    const float* __restrict__ V,
                                                    float* __restrict__ O) {
    __shared__ float Qs[64][65];
    __shared__ float Ks[32][65];
    __shared__ float Vs[32][65];
    __shared__ float Ss[64][33];
    __shared__ float m_s[64], l_s[64], al_s[64];

    const int tid = threadIdx.x;
    const int qi = blockIdx.x;
    const int bh = blockIdx.y;
    const int b  = bh >> 5;
    const int h  = bh & 31;
    const int hk = h >> 2;          // GQA: 4 q heads per kv head
    const int q0 = qi * 64;

    // load Q tile
    for (int i = tid; i < 64 * 64; i += 256) {
        int r = i >> 6, d = i & 63;
        Qs[r][d] = Q[(size_t)(b * T_ + q0 + r) * C_ + h * D_ + d];
    }
    if (tid < 64) { m_s[tid] = -INFINITY; l_s[tid] = 0.0f; }

    float acc[4][4];
#pragma unroll
    for (int i = 0; i < 4; ++i)
#pragma unroll
        for (int j = 0; j < 4; ++j) acc[i][j] = 0.0f;

    const int ty = tid >> 4;   // 0..15
    const int tx = tid & 15;   // 0..15

    __syncthreads();

    const int jmax = (q0 + 63) >> 5;
    for (int j = 0; j <= jmax; ++j) {
        const int k0 = j * 32;

        // load K,V tiles (32 x 64 each)
        for (int i = tid; i < 32 * 64; i += 256) {
            int r = i >> 6, d = i & 63;
            size_t g = (size_t)(b * T_ + k0 + r) * KVDIM + hk * D_ + d;
            Ks[r][d] = K[g];
            Vs[r][d] = V[g];
        }
        __syncthreads();

        // S = Q K^T  (64x32): thread computes rows ty*4..+3, cols tx*2..+1
        float sacc[4][2];
#pragma unroll
        for (int i = 0; i < 4; ++i) { sacc[i][0] = 0.0f; sacc[i][1] = 0.0f; }
#pragma unroll 8
        for (int kk = 0; kk < 64; ++kk) {
            float b0 = Ks[tx * 2 + 0][kk];
            float b1 = Ks[tx * 2 + 1][kk];
#pragma unroll
            for (int i = 0; i < 4; ++i) {
                float a = Qs[ty * 4 + i][kk];
                sacc[i][0] += a * b0;
                sacc[i][1] += a * b1;
            }
        }
#pragma unroll
        for (int i = 0; i < 4; ++i) {
            int r  = ty * 4 + i;
            int qg = q0 + r;
#pragma unroll
            for (int c = 0; c < 2; ++c) {
                int kg = k0 + tx * 2 + c;
                float vsc = sacc[i][c] * 0.125f;   // 1/sqrt(64)
                Ss[r][tx * 2 + c] = (kg > qg) ? -INFINITY : vsc;
            }
        }
        __syncthreads();

        // online softmax: one row per thread (threads 0..63)
        if (tid < 64) {
            float mo = m_s[tid];
            float mx = mo;
#pragma unroll
            for (int c = 0; c < 32; ++c) mx = fmaxf(mx, Ss[tid][c]);
            float al = __expf(mo - mx);            // exp(-inf)=0 on first tile
            float sum = 0.0f;
#pragma unroll
            for (int c = 0; c < 32; ++c) {
                float p = __expf(Ss[tid][c] - mx);
                Ss[tid][c] = p;
                sum += p;
            }
            l_s[tid]  = l_s[tid] * al + sum;
            m_s[tid]  = mx;
            al_s[tid] = al;
        }
        __syncthreads();

        // O = diag(alpha)*O + P V  (64x64): thread owns rows ty*4.., cols tx*4..
#pragma unroll
        for (int i = 0; i < 4; ++i) {
            float al = al_s[ty * 4 + i];
#pragma unroll
            for (int jj = 0; jj < 4; ++jj) acc[i][jj] *= al;
        }
#pragma unroll 4
        for (int kk = 0; kk < 32; ++kk) {
            float vv[4];
#pragma unroll
            for (int jj = 0; jj < 4; ++jj) vv[jj] = Vs[kk][tx * 4 + jj];
#pragma unroll
            for (int i = 0; i < 4; ++i) {
                float p = Ss[ty * 4 + i][kk];
#pragma unroll
                for (int jj = 0; jj < 4; ++jj) acc[i][jj] += p * vv[jj];
            }
        }
        __syncthreads();
    }

    // epilogue: divide by l, write [tok, H*D]
#pragma unroll
    for (int i = 0; i < 4; ++i) {
        int r = ty * 4 + i;
        float inv_l = 1.0f / l_s[r];
#pragma unroll
        for (int jj = 0; jj < 4; ++jj) {
            O[(size_t)(b * T_ + q0 + r) * C_ + h * D_ + tx * 4 + jj] =
                acc[i][jj] * inv_l;
        }
    }
}

// ---------------------------------------------------------------------------
extern "C" void kernel_launch(void* const* d_in, const int* in_sizes, int n_in,
                              void* d_out, int out_size) {
    const float* x  = (const float*)d_in[0];
    const float* Wq = (const float*)d_in[1];
    const float* Wk = (const float*)d_in[2];
    const float* Wv = (const float*)d_in[3];
    const float* Wp = (const float*)d_in[4];
    float* out = (float*)d_out;

    float *q, *k, *v, *att;
    cudaGetSymbolAddress((void**)&q,   g_q);
    cudaGetSymbolAddress((void**)&k,   g_k);
    cudaGetSymbolAddress((void**)&v,   g_v);
    cudaGetSymbolAddress((void**)&att, g_att);

    // QKV projections
    sgemm128<<<dim3(C_ / 128,    M_TOK / 128), 256>>>(x, Wq, q, M_TOK, C_,    C_);
    sgemm128<<<dim3(KVDIM / 128, M_TOK / 128), 256>>>(x, Wk, k, M_TOK, KVDIM, C_);
    sgemm128<<<dim3(KVDIM / 128, M_TOK / 128), 256>>>(x, Wv, v, M_TOK, KVDIM, C_);

    // RoPE on q and k (in-place)
    int total_pairs = M_TOK * (H_ + KV_) * (D_ / 2);
    rope_kernel<<<(total_pairs + 255) / 256, 256>>>(q, k);

    // causal flash attention with GQA
    flash_kernel<<<dim3(T_ / 64, B_ * H_), 256>>>(q, k, v, att);

    // output projection
    sgemm128<<<dim3(C_ / 128, M_TOK / 128), 256>>>(att, Wp, out, M_TOK, C_, C_);
}

// round 3
// speedup vs baseline: 2.0753x; 2.0753x over previous
#include <cuda_runtime.h>
#include <math.h>
#include <stdint.h>

#define B_    4
#define T_    1024
#define C_    2048
#define H_    32
#define KV_   8
#define D_    64
#define M_TOK (B_ * T_)          // 4096 tokens
#define KVDIM (KV_ * D_)         // 512

// ---------------- scratch (device globals; no allocation allowed) ----------
__device__ float g_q[M_TOK * C_];      // 32 MB  [tok, H*D]
__device__ float g_k[M_TOK * KVDIM];   //  8 MB  [tok, KV*D]
__device__ float g_v[M_TOK * KVDIM];   //  8 MB  [tok, KV*D]
__device__ float g_att[M_TOK * C_];    // 32 MB  [tok, H*D]

// ------------------------- tf32 helpers ------------------------------------
// cvt to tf32 needs a .b32 destination register in PTX.
__device__ __forceinline__ uint32_t to_tf32(float x) {
    uint32_t r;
    asm("cvt.rna.tf32.f32 %0, %1;" : "=r"(r) : "f"(x));
    return r;
}

__device__ __forceinline__ void mma_tf32(float c[4], const uint32_t a[4],
                                         const uint32_t b[2]) {
    asm volatile(
        "mma.sync.aligned.m16n8k8.row.col.f32.tf32.tf32.f32 "
        "{%0,%1,%2,%3}, {%4,%5,%6,%7}, {%8,%9}, {%0,%1,%2,%3};"
        : "+f"(c[0]), "+f"(c[1]), "+f"(c[2]), "+f"(c[3])
        : "r"(a[0]), "r"(a[1]), "r"(a[2]), "r"(a[3]), "r"(b[0]), "r"(b[1]));
}

// ---------------- tf32 tensor-core GEMM: C[M,N] = A[M,K] @ B[K,N] ----------
// 128x128x32 block tile, 8 warps (2x4), warp tile 64x32 (4x4 m16n8k8 tiles).
// Double-buffered dynamic smem; LDG->cvt.rna.tf32->STS staging.
#define AS_LD 36     // 32 + 4 pad  (A stored [m][k])
#define BS_LD 132    // 128 + 4 pad (B stored [k][n])
#define SMEM_GEMM ((2 * 128 * AS_LD + 2 * 32 * BS_LD) * 4)

__global__ void __launch_bounds__(256, 1)
sgemm_tc(const float* __restrict__ A, const float* __restrict__ B,
         float* __restrict__ C, int M, int N, int K) {
    extern __shared__ uint32_t sm[];
    uint32_t* As = sm;                      // [2][128][AS_LD]
    uint32_t* Bs = sm + 2 * 128 * AS_LD;    // [2][32][BS_LD]

    const int tid  = threadIdx.x;
    const int bm   = blockIdx.y * 128;
    const int bn   = blockIdx.x * 128;
    const int warp = tid >> 5;
    const int lane = tid & 31;
    const int g    = lane >> 2;          // group id 0..7
    const int tg   = lane & 3;           // thread-in-group 0..3
    const int wm   = (warp >> 2) * 64;   // warp m offset
    const int wn   = (warp & 3) * 32;    // warp n offset

    float4 aReg[4], bReg[4];

    float acc[4][4][4];
#pragma unroll
    for (int i = 0; i < 4; ++i)
#pragma unroll
        for (int j = 0; j < 4; ++j)
#pragma unroll
            for (int c = 0; c < 4; ++c) acc[i][j][c] = 0.0f;

    // ---- LDG of one k-slab into registers ----
#define LDG_TILE(kb)                                                        \
    do {                                                                    \
        _Pragma("unroll")                                                   \
        for (int l = 0; l < 4; ++l) {                                       \
            int f = l * 256 + tid;                                          \
            aReg[l] = *(const float4*)(A + (size_t)(bm + (f >> 3)) * K +    \
                                       (kb) + ((f & 7) << 2));              \
            bReg[l] = *(const float4*)(B + (size_t)((kb) + (f >> 5)) * N +  \
                                       bn + ((f & 31) << 2));               \
        }                                                                   \
    } while (0)

    // ---- cvt + STS into stage s ----
#define STS_TILE(s)                                                         \
    do {                                                                    \
        uint32_t* ap = As + (s) * (128 * AS_LD);                            \
        uint32_t* bp = Bs + (s) * (32 * BS_LD);                             \
        _Pragma("unroll")                                                   \
        for (int l = 0; l < 4; ++l) {                                       \
            int f = l * 256 + tid;                                          \
            int ar = f >> 3, ac = (f & 7) << 2;                             \
            ap[ar * AS_LD + ac + 0] = to_tf32(aReg[l].x);                   \
            ap[ar * AS_LD + ac + 1] = to_tf32(aReg[l].y);                   \
            ap[ar * AS_LD + ac + 2] = to_tf32(aReg[l].z);                   \
            ap[ar * AS_LD + ac + 3] = to_tf32(aReg[l].w);                   \
            int br = f >> 5, bc = (f & 31) << 2;                            \
            bp[br * BS_LD + bc + 0] = to_tf32(bReg[l].x);                   \
            bp[br * BS_LD + bc + 1] = to_tf32(bReg[l].y);                   \
            bp[br * BS_LD + bc + 2] = to_tf32(bReg[l].z);                   \
            bp[br * BS_LD + bc + 3] = to_tf32(bReg[l].w);                   \
        }                                                                   \
    } while (0)

    LDG_TILE(0);
    STS_TILE(0);
    __syncthreads();

    for (int kb = 0; kb < K; kb += 32) {
        const int s = (kb >> 5) & 1;
        const bool more = (kb + 32) < K;
        if (more) LDG_TILE(kb + 32);

        const uint32_t* a_s = As + s * (128 * AS_LD);
        const uint32_t* b_s = Bs + s * (32 * BS_LD);

#pragma unroll
        for (int ks = 0; ks < 32; ks += 8) {
            uint32_t af[4][4], bf[4][2];
#pragma unroll
            for (int mt = 0; mt < 4; ++mt) {
                int m0 = wm + mt * 16;
                af[mt][0] = a_s[(m0 + g)     * AS_LD + ks + tg];
                af[mt][1] = a_s[(m0 + g + 8) * AS_LD + ks + tg];
                af[mt][2] = a_s[(m0 + g)     * AS_LD + ks + tg + 4];
                af[mt][3] = a_s[(m0 + g + 8) * AS_LD + ks + tg + 4];
            }
#pragma unroll
            for (int nt = 0; nt < 4; ++nt) {
                int n0 = wn + nt * 8;
                bf[nt][0] = b_s[(ks + tg)     * BS_LD + n0 + g];
                bf[nt][1] = b_s[(ks + tg + 4) * BS_LD + n0 + g];
            }
#pragma unroll
            for (int mt = 0; mt < 4; ++mt)
#pragma unroll
                for (int nt = 0; nt < 4; ++nt)
                    mma_tf32(acc[mt][nt], af[mt], bf[nt]);
        }

        if (more) STS_TILE(s ^ 1);
        __syncthreads();
    }

    // epilogue: c0:(g, tg*2) c1:(g, tg*2+1) c2:(g+8, tg*2) c3:(g+8, tg*2+1)
#pragma unroll
    for (int mt = 0; mt < 4; ++mt) {
#pragma unroll
        for (int nt = 0; nt < 4; ++nt) {
            int r0  = bm + wm + mt * 16 + g;
            int col = bn + wn + nt * 8 + tg * 2;
            float2 lo = make_float2(acc[mt][nt][0], acc[mt][nt][1]);
            float2 hi = make_float2(acc[mt][nt][2], acc[mt][nt][3]);
            *(float2*)(C + (size_t)r0 * N + col)       = lo;
            *(float2*)(C + (size_t)(r0 + 8) * N + col) = hi;
        }
    }
}

// ---------------- RoPE (interleaved pairs), applied in-place to q and k ----
__global__ void rope_kernel(float* __restrict__ q, float* __restrict__ k) {
    const int NH = H_ + KV_;   // 40 heads total (32 q + 8 k)
    int idx = blockIdx.x * blockDim.x + threadIdx.x;
    const int total = M_TOK * NH * (D_ / 2);
    if (idx >= total) return;

    int p   = idx & 31;                 // pair index 0..31
    int hh  = (idx >> 5) % NH;          // head index (q heads then k heads)
    int tok = idx / (32 * NH);          // global token 0..4095
    int tseq = tok & (T_ - 1);          // position within sequence

    float inv = powf(10000.0f, -(float)p / 32.0f);
    float ang = (float)tseq * inv;
    float s, c;
    sincosf(ang, &s, &c);

    float* base = (hh < H_) ? (q + (size_t)tok * C_ + hh * D_)
                            : (k + (size_t)tok * KVDIM + (hh - H_) * D_);
    float e0 = base[2 * p];
    float e1 = base[2 * p + 1];
    base[2 * p]     = e0 * c - e1 * s;
    base[2 * p + 1] = e1 * c + e0 * s;
}

// ---------------- causal flash attention with GQA (rf=4) -------------------
__global__ void __launch_bounds__(256) flash_kernel(const float* __restrict__ Q,
                                                    const float* __restrict__ K,
                                                    const float* __restrict__ V,
                                                    float* __restrict__ O) {
    __shared__ float Qs[64][65];
    __shared__ float Ks[32][65];
    __shared__ float Vs[32][65];
    __shared__ float Ss[64][33];
    __shared__ float m_s[64], l_s[64], al_s[64];

    const int tid = threadIdx.x;
    const int qi = blockIdx.x;
    const int bh = blockIdx.y;
    const int b  = bh >> 5;
    const int h  = bh & 31;
    const int hk = h >> 2;          // GQA: 4 q heads per kv head
    const int q0 = qi * 64;

    for (int i = tid; i < 64 * 64; i += 256) {
        int r = i >> 6, d = i & 63;
        Qs[r][d] = Q[(size_t)(b * T_ + q0 + r) * C_ + h * D_ + d];
    }
    if (tid < 64) { m_s[tid] = -INFINITY; l_s[tid] = 0.0f; }

    float acc[4][4];
#pragma unroll
    for (int i = 0; i < 4; ++i)
#pragma unroll
        for (int j = 0; j < 4; ++j) acc[i][j] = 0.0f;

    const int ty = tid >> 4;   // 0..15
    const int tx = tid & 15;   // 0..15

    __syncthreads();

    const int jmax = (q0 + 63) >> 5;
    for (int j = 0; j <= jmax; ++j) {
        const int k0 = j * 32;

        for (int i = tid; i < 32 * 64; i += 256) {
            int r = i >> 6, d = i & 63;
            size_t gidx = (size_t)(b * T_ + k0 + r) * KVDIM + hk * D_ + d;
            Ks[r][d] = K[gidx];
            Vs[r][d] = V[gidx];
        }
        __syncthreads();

        float sacc[4][2];
#pragma unroll
        for (int i = 0; i < 4; ++i) { sacc[i][0] = 0.0f; sacc[i][1] = 0.0f; }
#pragma unroll 8
        for (int kk = 0; kk < 64; ++kk) {
            float b0 = Ks[tx * 2 + 0][kk];
            float b1 = Ks[tx * 2 + 1][kk];
#pragma unroll
            for (int i = 0; i < 4; ++i) {
                float a = Qs[ty * 4 + i][kk];
                sacc[i][0] += a * b0;
                sacc[i][1] += a * b1;
            }
        }
#pragma unroll
        for (int i = 0; i < 4; ++i) {
            int r  = ty * 4 + i;
            int qg = q0 + r;
#pragma unroll
            for (int c = 0; c < 2; ++c) {
                int kg = k0 + tx * 2 + c;
                float vsc = sacc[i][c] * 0.125f;   // 1/sqrt(64)
                Ss[r][tx * 2 + c] = (kg > qg) ? -INFINITY : vsc;
            }
        }
        __syncthreads();

        if (tid < 64) {
            float mo = m_s[tid];
            float mx = mo;
#pragma unroll
            for (int c = 0; c < 32; ++c) mx = fmaxf(mx, Ss[tid][c]);
            float al = __expf(mo - mx);
            float sum = 0.0f;
#pragma unroll
            for (int c = 0; c < 32; ++c) {
                float p = __expf(Ss[tid][c] - mx);
                Ss[tid][c] = p;
                sum += p;
            }
            l_s[tid]  = l_s[tid] * al + sum;
            m_s[tid]  = mx;
            al_s[tid] = al;
        }
        __syncthreads();

#pragma unroll
        for (int i = 0; i < 4; ++i) {
            float al = al_s[ty * 4 + i];
#pragma unroll
            for (int jj = 0; jj < 4; ++jj) acc[i][jj] *= al;
        }
#pragma unroll 4
        for (int kk = 0; kk < 32; ++kk) {
            float vv[4];
#pragma unroll
            for (int jj = 0; jj < 4; ++jj) vv[jj] = Vs[kk][tx * 4 + jj];
#pragma unroll
            for (int i = 0; i < 4; ++i) {
                float p = Ss[ty * 4 + i][kk];
#pragma unroll
                for (int jj = 0; jj < 4; ++jj) acc[i][jj] += p * vv[jj];
            }
        }
        __syncthreads();
    }

#pragma unroll
    for (int i = 0; i < 4; ++i) {
        int r = ty * 4 + i;
        float inv_l = 1.0f / l_s[r];
#pragma unroll
        for (int jj = 0; jj < 4; ++jj) {
            O[(size_t)(b * T_ + q0 + r) * C_ + h * D_ + tx * 4 + jj] =
                acc[i][jj] * inv_l;
        }
    }
}

// ---------------------------------------------------------------------------
extern "C" void kernel_launch(void* const* d_in, const int* in_sizes, int n_in,
                              void* d_out, int out_size) {
    const float* x  = (const float*)d_in[0];
    const float* Wq = (const float*)d_in[1];
    const float* Wk = (const float*)d_in[2];
    const float* Wv = (const float*)d_in[3];
    const float* Wp = (const float*)d_in[4];
    float* out = (float*)d_out;

    float *q, *k, *v, *att;
    cudaGetSymbolAddress((void**)&q,   g_q);
    cudaGetSymbolAddress((void**)&k,   g_k);
    cudaGetSymbolAddress((void**)&v,   g_v);
    cudaGetSymbolAddress((void**)&att, g_att);

    cudaFuncSetAttribute(sgemm_tc, cudaFuncAttributeMaxDynamicSharedMemorySize,
                         SMEM_GEMM);

    // QKV projections (tf32 tensor cores)
    sgemm_tc<<<dim3(C_ / 128,    M_TOK / 128), 256, SMEM_GEMM>>>(x, Wq, q, M_TOK, C_,    C_);
    sgemm_tc<<<dim3(KVDIM / 128, M_TOK / 128), 256, SMEM_GEMM>>>(x, Wk, k, M_TOK, KVDIM, C_);
    sgemm_tc<<<dim3(KVDIM / 128, M_TOK / 128), 256, SMEM_GEMM>>>(x, Wv, v, M_TOK, KVDIM, C_);

    // RoPE on q and k (in-place)
    int total_pairs = M_TOK * (H_ + KV_) * (D_ / 2);
    rope_kernel<<<(total_pairs + 255) / 256, 256>>>(q, k);

    // causal flash attention with GQA
    flash_kernel<<<dim3(T_ / 64, B_ * H_), 256>>>(q, k, v, att);

    // output projection (tf32 tensor cores)
    sgemm_tc<<<dim3(C_ / 128, M_TOK / 128), 256, SMEM_GEMM>>>(att, Wp, out, M_TOK, C_, C_);
}

// round 4
// speedup vs baseline: 3.1572x; 1.5213x over previous
#include <cuda_runtime.h>
#include <math.h>
#include <stdint.h>

#define B_    4
#define T_    1024
#define C_    2048
#define H_    32
#define KV_   8
#define D_    64
#define M_TOK (B_ * T_)          // 4096 tokens
#define KVDIM (KV_ * D_)         // 512

// ---------------- scratch (device globals; no allocation allowed) ----------
__device__ float g_q[M_TOK * C_];      // 32 MB  [tok, H*D]
__device__ float g_k[M_TOK * KVDIM];   //  8 MB  [tok, KV*D]
__device__ float g_v[M_TOK * KVDIM];   //  8 MB  [tok, KV*D]
__device__ float g_att[M_TOK * C_];    // 32 MB  [tok, H*D]

// ------------------------- tf32 helpers ------------------------------------
__device__ __forceinline__ uint32_t to_tf32(float x) {
    uint32_t r;
    asm("cvt.rna.tf32.f32 %0, %1;" : "=r"(r) : "f"(x));
    return r;
}

__device__ __forceinline__ float ex2f(float x) {
    float r;
    asm("ex2.approx.f32 %0, %1;" : "=f"(r) : "f"(x));
    return r;
}

__device__ __forceinline__ void mma_tf32(float c[4], const uint32_t a[4],
                                         const uint32_t b[2]) {
    asm volatile(
        "mma.sync.aligned.m16n8k8.row.col.f32.tf32.tf32.f32 "
        "{%0,%1,%2,%3}, {%4,%5,%6,%7}, {%8,%9}, {%0,%1,%2,%3};"
        : "+f"(c[0]), "+f"(c[1]), "+f"(c[2]), "+f"(c[3])
        : "r"(a[0]), "r"(a[1]), "r"(a[2]), "r"(a[3]), "r"(b[0]), "r"(b[1]));
}

// ---------------- tf32 tensor-core GEMM: C[M,N] = A[M,K] @ B[K,N] ----------
#define AS_LD 36
#define BS_LD 132
#define SMEM_GEMM ((2 * 128 * AS_LD + 2 * 32 * BS_LD) * 4)

__global__ void __launch_bounds__(256, 1)
sgemm_tc(const float* __restrict__ A, const float* __restrict__ B,
         float* __restrict__ C, int M, int N, int K) {
    extern __shared__ uint32_t sm[];
    uint32_t* As = sm;                      // [2][128][AS_LD]
    uint32_t* Bs = sm + 2 * 128 * AS_LD;    // [2][32][BS_LD]

    const int tid  = threadIdx.x;
    const int bm   = blockIdx.y * 128;
    const int bn   = blockIdx.x * 128;
    const int warp = tid >> 5;
    const int lane = tid & 31;
    const int g    = lane >> 2;
    const int tg   = lane & 3;
    const int wm   = (warp >> 2) * 64;
    const int wn   = (warp & 3) * 32;

    float4 aReg[4], bReg[4];

    float acc[4][4][4];
#pragma unroll
    for (int i = 0; i < 4; ++i)
#pragma unroll
        for (int j = 0; j < 4; ++j)
#pragma unroll
            for (int c = 0; c < 4; ++c) acc[i][j][c] = 0.0f;

#define LDG_TILE(kb)                                                        \
    do {                                                                    \
        _Pragma("unroll")                                                   \
        for (int l = 0; l < 4; ++l) {                                       \
            int f = l * 256 + tid;                                          \
            aReg[l] = *(const float4*)(A + (size_t)(bm + (f >> 3)) * K +    \
                                       (kb) + ((f & 7) << 2));              \
            bReg[l] = *(const float4*)(B + (size_t)((kb) + (f >> 5)) * N +  \
                                       bn + ((f & 31) << 2));               \
        }                                                                   \
    } while (0)

#define STS_TILE(s)                                                         \
    do {                                                                    \
        uint32_t* ap = As + (s) * (128 * AS_LD);                            \
        uint32_t* bp = Bs + (s) * (32 * BS_LD);                             \
        _Pragma("unroll")                                                   \
        for (int l = 0; l < 4; ++l) {                                       \
            int f = l * 256 + tid;                                          \
            int ar = f >> 3, ac = (f & 7) << 2;                             \
            ap[ar * AS_LD + ac + 0] = to_tf32(aReg[l].x);                   \
            ap[ar * AS_LD + ac + 1] = to_tf32(aReg[l].y);                   \
            ap[ar * AS_LD + ac + 2] = to_tf32(aReg[l].z);                   \
            ap[ar * AS_LD + ac + 3] = to_tf32(aReg[l].w);                   \
            int br = f >> 5, bc = (f & 31) << 2;                            \
            bp[br * BS_LD + bc + 0] = to_tf32(bReg[l].x);                   \
            bp[br * BS_LD + bc + 1] = to_tf32(bReg[l].y);                   \
            bp[br * BS_LD + bc + 2] = to_tf32(bReg[l].z);                   \
            bp[br * BS_LD + bc + 3] = to_tf32(bReg[l].w);                   \
        }                                                                   \
    } while (0)

    LDG_TILE(0);
    STS_TILE(0);
    __syncthreads();

    for (int kb = 0; kb < K; kb += 32) {
        const int s = (kb >> 5) & 1;
        const bool more = (kb + 32) < K;
        if (more) LDG_TILE(kb + 32);

        const uint32_t* a_s = As + s * (128 * AS_LD);
        const uint32_t* b_s = Bs + s * (32 * BS_LD);

#pragma unroll
        for (int ks = 0; ks < 32; ks += 8) {
            uint32_t af[4][4], bf[4][2];
#pragma unroll
            for (int mt = 0; mt < 4; ++mt) {
                int m0 = wm + mt * 16;
                af[mt][0] = a_s[(m0 + g)     * AS_LD + ks + tg];
                af[mt][1] = a_s[(m0 + g + 8) * AS_LD + ks + tg];
                af[mt][2] = a_s[(m0 + g)     * AS_LD + ks + tg + 4];
                af[mt][3] = a_s[(m0 + g + 8) * AS_LD + ks + tg + 4];
            }
#pragma unroll
            for (int nt = 0; nt < 4; ++nt) {
                int n0 = wn + nt * 8;
                bf[nt][0] = b_s[(ks + tg)     * BS_LD + n0 + g];
                bf[nt][1] = b_s[(ks + tg + 4) * BS_LD + n0 + g];
            }
#pragma unroll
            for (int mt = 0; mt < 4; ++mt)
#pragma unroll
                for (int nt = 0; nt < 4; ++nt)
                    mma_tf32(acc[mt][nt], af[mt], bf[nt]);
        }

        if (more) STS_TILE(s ^ 1);
        __syncthreads();
    }

#pragma unroll
    for (int mt = 0; mt < 4; ++mt) {
#pragma unroll
        for (int nt = 0; nt < 4; ++nt) {
            int r0  = bm + wm + mt * 16 + g;
            int col = bn + wn + nt * 8 + tg * 2;
            float2 lo = make_float2(acc[mt][nt][0], acc[mt][nt][1]);
            float2 hi = make_float2(acc[mt][nt][2], acc[mt][nt][3]);
            *(float2*)(C + (size_t)r0 * N + col)       = lo;
            *(float2*)(C + (size_t)(r0 + 8) * N + col) = hi;
        }
    }
}

// ---------------- RoPE (interleaved pairs), applied in-place to q and k ----
__global__ void rope_kernel(float* __restrict__ q, float* __restrict__ k) {
    const int NH = H_ + KV_;
    int idx = blockIdx.x * blockDim.x + threadIdx.x;
    const int total = M_TOK * NH * (D_ / 2);
    if (idx >= total) return;

    int p   = idx & 31;
    int hh  = (idx >> 5) % NH;
    int tok = idx / (32 * NH);
    int tseq = tok & (T_ - 1);

    float inv = powf(10000.0f, -(float)p / 32.0f);
    float ang = (float)tseq * inv;
    float s, c;
    sincosf(ang, &s, &c);

    float* base = (hh < H_) ? (q + (size_t)tok * C_ + hh * D_)
                            : (k + (size_t)tok * KVDIM + (hh - H_) * D_);
    float e0 = base[2 * p];
    float e1 = base[2 * p + 1];
    base[2 * p]     = e0 * c - e1 * s;
    base[2 * p + 1] = e1 * c + e0 * s;
}

// ---------------- tf32 tensor-core causal flash attention (GQA rf=4) -------
// 128 threads / 4 warps. BQ=64 (16 rows per warp), BK=64, D=64.
// Q held in registers (tf32) for the whole kernel; softmax in exp2 domain.
#define FLD 68
#define SMEM_FLASH (3 * 64 * FLD * 4)

__global__ void __launch_bounds__(128, 3)
flash_tc(const float* __restrict__ Q, const float* __restrict__ K,
         const float* __restrict__ V, float* __restrict__ O) {
    extern __shared__ uint32_t fsm[];
    uint32_t* Ks = fsm;                 // [64][FLD] tf32
    uint32_t* Vs = fsm + 64 * FLD;      // [64][FLD] tf32
    uint32_t* Ps = fsm + 2 * 64 * FLD;  // [64][FLD] tf32 (Q staging, then P)

    const int tid  = threadIdx.x;
    const int warp = tid >> 5;
    const int lane = tid & 31;
    const int g    = lane >> 2;
    const int tg   = lane & 3;

    const int qi = blockIdx.x;
    const int bh = blockIdx.y;
    const int b  = bh >> 5;
    const int h  = bh & 31;
    const int hk = h >> 2;
    const int q0 = qi * 64;
    const int qrow = warp * 16;

    const float SC = 0.125f * 1.4426950408889634f;  // 1/sqrt(D) * log2(e)

    // stage scaled Q (tf32) into Ps, then load fragments to registers
    for (int i = tid; i < 1024; i += 128) {
        int r = i >> 4, c = (i & 15) << 2;
        float4 qv = *(const float4*)(Q + (size_t)(b * T_ + q0 + r) * C_ +
                                     h * D_ + c);
        uint32_t* p = Ps + r * FLD + c;
        p[0] = to_tf32(qv.x * SC);
        p[1] = to_tf32(qv.y * SC);
        p[2] = to_tf32(qv.z * SC);
        p[3] = to_tf32(qv.w * SC);
    }
    __syncthreads();

    uint32_t qf[8][4];
#pragma unroll
    for (int ks = 0; ks < 8; ++ks) {
        qf[ks][0] = Ps[(qrow + g)     * FLD + ks * 8 + tg];
        qf[ks][1] = Ps[(qrow + g + 8) * FLD + ks * 8 + tg];
        qf[ks][2] = Ps[(qrow + g)     * FLD + ks * 8 + tg + 4];
        qf[ks][3] = Ps[(qrow + g + 8) * FLD + ks * 8 + tg + 4];
    }

    float m1 = -INFINITY, m2 = -INFINITY, l1 = 0.0f, l2 = 0.0f;
    float oacc[8][4];
#pragma unroll
    for (int nt = 0; nt < 8; ++nt)
#pragma unroll
        for (int c = 0; c < 4; ++c) oacc[nt][c] = 0.0f;

    for (int j = 0; j <= qi; ++j) {
        const int k0 = j * 64;
        __syncthreads();   // protect Ks/Vs/Ps from previous iteration readers

        for (int i = tid; i < 1024; i += 128) {
            int r = i >> 4, c = (i & 15) << 2;
            size_t gb = (size_t)(b * T_ + k0 + r) * KVDIM + hk * D_ + c;
            float4 kv = *(const float4*)(K + gb);
            float4 vv = *(const float4*)(V + gb);
            uint32_t* pk = Ks + r * FLD + c;
            uint32_t* pv = Vs + r * FLD + c;
            pk[0] = to_tf32(kv.x); pk[1] = to_tf32(kv.y);
            pk[2] = to_tf32(kv.z); pk[3] = to_tf32(kv.w);
            pv[0] = to_tf32(vv.x); pv[1] = to_tf32(vv.y);
            pv[2] = to_tf32(vv.z); pv[3] = to_tf32(vv.w);
        }
        __syncthreads();

        // S = Q K^T  (16x64 per warp, in exp2 domain already via SC)
        float sacc[8][4];
#pragma unroll
        for (int nt = 0; nt < 8; ++nt)
#pragma unroll
            for (int c = 0; c < 4; ++c) sacc[nt][c] = 0.0f;

#pragma unroll
        for (int nt = 0; nt < 8; ++nt) {
#pragma unroll
            for (int ks = 0; ks < 8; ++ks) {
                uint32_t bf[2];
                bf[0] = Ks[(nt * 8 + g) * FLD + ks * 8 + tg];
                bf[1] = Ks[(nt * 8 + g) * FLD + ks * 8 + tg + 4];
                mma_tf32(sacc[nt], qf[ks], bf);
            }
        }

        // causal mask (diagonal tile only)
        if (j == qi) {
            int r1 = q0 + qrow + g, r2 = r1 + 8;
#pragma unroll
            for (int nt = 0; nt < 8; ++nt) {
                int c0 = k0 + nt * 8 + tg * 2;
                if (c0     > r1) sacc[nt][0] = -INFINITY;
                if (c0 + 1 > r1) sacc[nt][1] = -INFINITY;
                if (c0     > r2) sacc[nt][2] = -INFINITY;
                if (c0 + 1 > r2) sacc[nt][3] = -INFINITY;
            }
        }

        // row max (local over 16 vals, then quad shuffle)
        float a1 = -INFINITY, a2 = -INFINITY;
#pragma unroll
        for (int nt = 0; nt < 8; ++nt) {
            a1 = fmaxf(a1, fmaxf(sacc[nt][0], sacc[nt][1]));
            a2 = fmaxf(a2, fmaxf(sacc[nt][2], sacc[nt][3]));
        }
        a1 = fmaxf(a1, __shfl_xor_sync(0xffffffff, a1, 1));
        a1 = fmaxf(a1, __shfl_xor_sync(0xffffffff, a1, 2));
        a2 = fmaxf(a2, __shfl_xor_sync(0xffffffff, a2, 1));
        a2 = fmaxf(a2, __shfl_xor_sync(0xffffffff, a2, 2));

        float mn1 = fmaxf(m1, a1), mn2 = fmaxf(m2, a2);
        float al1 = ex2f(m1 - mn1), al2 = ex2f(m2 - mn2);

        // p = exp2(s - m); accumulate row sums; store P (tf32) to smem
        float s1 = 0.0f, s2 = 0.0f;
#pragma unroll
        for (int nt = 0; nt < 8; ++nt) {
            float p0 = ex2f(sacc[nt][0] - mn1);
            float p1 = ex2f(sacc[nt][1] - mn1);
            float p2 = ex2f(sacc[nt][2] - mn2);
            float p3 = ex2f(sacc[nt][3] - mn2);
            s1 += p0 + p1;
            s2 += p2 + p3;
            int col = nt * 8 + tg * 2;
            Ps[(qrow + g)     * FLD + col]     = to_tf32(p0);
            Ps[(qrow + g)     * FLD + col + 1] = to_tf32(p1);
            Ps[(qrow + g + 8) * FLD + col]     = to_tf32(p2);
            Ps[(qrow + g + 8) * FLD + col + 1] = to_tf32(p3);
        }
        s1 += __shfl_xor_sync(0xffffffff, s1, 1);
        s1 += __shfl_xor_sync(0xffffffff, s1, 2);
        s2 += __shfl_xor_sync(0xffffffff, s2, 1);
        s2 += __shfl_xor_sync(0xffffffff, s2, 2);

        l1 = l1 * al1 + s1;
        l2 = l2 * al2 + s2;
        m1 = mn1;
        m2 = mn2;

#pragma unroll
        for (int nt = 0; nt < 8; ++nt) {
            oacc[nt][0] *= al1; oacc[nt][1] *= al1;
            oacc[nt][2] *= al2; oacc[nt][3] *= al2;
        }
        __syncwarp();

        // O += P V
#pragma unroll
        for (int ks = 0; ks < 8; ++ks) {
            uint32_t af[4];
            af[0] = Ps[(qrow + g)     * FLD + ks * 8 + tg];
            af[1] = Ps[(qrow + g + 8) * FLD + ks * 8 + tg];
            af[2] = Ps[(qrow + g)     * FLD + ks * 8 + tg + 4];
            af[3] = Ps[(qrow + g + 8) * FLD + ks * 8 + tg + 4];
#pragma unroll
            for (int nt = 0; nt < 8; ++nt) {
                uint32_t bf[2];
                bf[0] = Vs[(ks * 8 + tg)     * FLD + nt * 8 + g];
                bf[1] = Vs[(ks * 8 + tg + 4) * FLD + nt * 8 + g];
                mma_tf32(oacc[nt], af, bf);
            }
        }
        __syncwarp();
    }

    // epilogue: normalize and write [tok, H*D]
    float i1 = 1.0f / l1, i2 = 1.0f / l2;
    int r1 = q0 + qrow + g, r2 = r1 + 8;
#pragma unroll
    for (int nt = 0; nt < 8; ++nt) {
        int col = h * D_ + nt * 8 + tg * 2;
        float2 lo = make_float2(oacc[nt][0] * i1, oacc[nt][1] * i1);
        float2 hi = make_float2(oacc[nt][2] * i2, oacc[nt][3] * i2);
        *(float2*)(O + (size_t)(b * T_ + r1) * C_ + col) = lo;
        *(float2*)(O + (size_t)(b * T_ + r2) * C_ + col) = hi;
    }
}

// ---------------------------------------------------------------------------
extern "C" void kernel_launch(void* const* d_in, const int* in_sizes, int n_in,
                              void* d_out, int out_size) {
    const float* x  = (const float*)d_in[0];
    const float* Wq = (const float*)d_in[1];
    const float* Wk = (const float*)d_in[2];
    const float* Wv = (const float*)d_in[3];
    const float* Wp = (const float*)d_in[4];
    float* out = (float*)d_out;

    float *q, *k, *v, *att;
    cudaGetSymbolAddress((void**)&q,   g_q);
    cudaGetSymbolAddress((void**)&k,   g_k);
    cudaGetSymbolAddress((void**)&v,   g_v);
    cudaGetSymbolAddress((void**)&att, g_att);

    cudaFuncSetAttribute(sgemm_tc, cudaFuncAttributeMaxDynamicSharedMemorySize,
                         SMEM_GEMM);
    cudaFuncSetAttribute(flash_tc, cudaFuncAttributeMaxDynamicSharedMemorySize,
                         SMEM_FLASH);

    // QKV projections (tf32 tensor cores)
    sgemm_tc<<<dim3(C_ / 128,    M_TOK / 128), 256, SMEM_GEMM>>>(x, Wq, q, M_TOK, C_,    C_);
    sgemm_tc<<<dim3(KVDIM / 128, M_TOK / 128), 256, SMEM_GEMM>>>(x, Wk, k, M_TOK, KVDIM, C_);
    sgemm_tc<<<dim3(KVDIM / 128, M_TOK / 128), 256, SMEM_GEMM>>>(x, Wv, v, M_TOK, KVDIM, C_);

    // RoPE on q and k (in-place)
    int total_pairs = M_TOK * (H_ + KV_) * (D_ / 2);
    rope_kernel<<<(total_pairs + 255) / 256, 256>>>(q, k);

    // causal flash attention with GQA (tf32 tensor cores)
    flash_tc<<<dim3(T_ / 64, B_ * H_), 128, SMEM_FLASH>>>(q, k, v, att);

    // output projection (tf32 tensor cores)
    sgemm_tc<<<dim3(C_ / 128, M_TOK / 128), 256, SMEM_GEMM>>>(att, Wp, out, M_TOK, C_, C_);
}

// round 6
// speedup vs baseline: 3.7585x; 1.1904x over previous
#include <cuda_runtime.h>
#include <math.h>
#include <stdint.h>

#define B_    4
#define T_    1024
#define C_    2048
#define H_    32
#define KV_   8
#define D_    64
#define M_TOK 4096
#define KVDIM 512
#define NQKV  3072          // 2048 q + 512 k + 512 v

// ---------------- scratch (device globals; no allocation allowed) ----------
__device__ float g_q[M_TOK * C_];        // 32 MB
__device__ float g_k[M_TOK * KVDIM];     //  8 MB
__device__ float g_v[M_TOK * KVDIM];     //  8 MB
__device__ float g_att[M_TOK * C_];      // 32 MB
__device__ float g_xc[M_TOK * C_];       // 32 MB  tf32(x)
__device__ float g_wqkv[C_ * NQKV];      // 24 MB  tf32([Wq|Wk|Wv]) [k][n]
__device__ float g_wpc[C_ * C_];         // 16 MB  tf32(Wp)

// ------------------------- helpers -----------------------------------------
__device__ __forceinline__ uint32_t to_tf32(float x) {
    uint32_t r;
    asm("cvt.rna.tf32.f32 %0, %1;" : "=r"(r) : "f"(x));
    return r;
}
__device__ __forceinline__ float tf32f(float x) {
    return __uint_as_float(to_tf32(x));
}
__device__ __forceinline__ float ex2f(float x) {
    float r;
    asm("ex2.approx.f32 %0, %1;" : "=f"(r) : "f"(x));
    return r;
}
__device__ __forceinline__ void mma_tf32(float c[4], const uint32_t a[4],
                                         const uint32_t b[2]) {
    asm volatile(
        "mma.sync.aligned.m16n8k8.row.col.f32.tf32.tf32.f32 "
        "{%0,%1,%2,%3}, {%4,%5,%6,%7}, {%8,%9}, {%0,%1,%2,%3};"
        : "+f"(c[0]), "+f"(c[1]), "+f"(c[2]), "+f"(c[3])
        : "r"(a[0]), "r"(a[1]), "r"(a[2]), "r"(a[3]), "r"(b[0]), "r"(b[1]));
}
__device__ __forceinline__ uint32_t smem_u32(const void* p) {
    uint32_t a;
    asm("{ .reg .u64 t; cvta.to.shared.u64 t, %1; cvt.u32.u64 %0, t; }"
        : "=r"(a) : "l"(p));
    return a;
}
__device__ __forceinline__ void cpa16(uint32_t dst, const void* src) {
    asm volatile("cp.async.cg.shared.global [%0], [%1], 16;"
                 :: "r"(dst), "l"(src) : "memory");
}
__device__ __forceinline__ void cpa_commit() {
    asm volatile("cp.async.commit_group;" ::: "memory");
}
template <int N> __device__ __forceinline__ void cpa_wait() {
    asm volatile("cp.async.wait_group %0;" :: "n"(N) : "memory");
}

// ---------------- tf32 pre-conversion / weight packing ---------------------
__global__ void cvt_pack(const float* __restrict__ x,
                         const float* __restrict__ Wq,
                         const float* __restrict__ Wk,
                         const float* __restrict__ Wv,
                         const float* __restrict__ Wp) {
    int i4 = blockIdx.x * blockDim.x + threadIdx.x;

    if (i4 < M_TOK * C_ / 4) {
        float4 v = ((const float4*)x)[i4];
        v.x = tf32f(v.x); v.y = tf32f(v.y); v.z = tf32f(v.z); v.w = tf32f(v.w);
        ((float4*)g_xc)[i4] = v;
    }
    if (i4 < C_ * C_ / 4) {
        float4 v = ((const float4*)Wp)[i4];
        v.x = tf32f(v.x); v.y = tf32f(v.y); v.z = tf32f(v.z); v.w = tf32f(v.w);
        ((float4*)g_wpc)[i4] = v;
    }
    if (i4 < C_ * NQKV / 4) {
        int k = i4 / (NQKV / 4);
        int n = (i4 % (NQKV / 4)) * 4;
        const float* src = (n < 2048) ? Wq + (size_t)k * 2048 + n
                         : (n < 2560) ? Wk + (size_t)k * 512 + (n - 2048)
                                      : Wv + (size_t)k * 512 + (n - 2560);
        float4 v = *(const float4*)src;
        v.x = tf32f(v.x); v.y = tf32f(v.y); v.z = tf32f(v.z); v.w = tf32f(v.w);
        ((float4*)g_wqkv)[i4] = v;
    }
}

// ============ cp.async 3-stage tf32 GEMM: C[M,N] = A[M,K] @ B[K,N] =========
// 128x128x32 tile, 8 warps (2x4), warp tile 64x32, m16n8k8.
// Inputs already tf32-valued f32 -> no cvt in mainloop.
#define AS_LD 36
#define BS_LD 132
#define STG_W (128 * AS_LD + 32 * BS_LD)   // 8832 words/stage
#define SMEM_G (3 * STG_W * 4)             // 105984 B

template <int SPLIT>
__global__ void __launch_bounds__(256)
gemm_cp(const float* __restrict__ A, const float* __restrict__ Bm,
        float* __restrict__ C0, int M, int N, int K) {
    extern __shared__ uint32_t sm[];

    const int tid  = threadIdx.x;
    const int bm   = blockIdx.y * 128;
    const int bn   = blockIdx.x * 128;
    const int warp = tid >> 5;
    const int lane = tid & 31;
    const int g    = lane >> 2;
    const int tg   = lane & 3;
    const int wm   = (warp >> 2) * 64;
    const int wn   = (warp & 3) * 32;
    const int nslab = K >> 5;

    const uint32_t sbase = smem_u32(sm);

    float acc[4][4][4];
#pragma unroll
    for (int i = 0; i < 4; ++i)
#pragma unroll
        for (int j = 0; j < 4; ++j)
#pragma unroll
            for (int c = 0; c < 4; ++c) acc[i][j][c] = 0.0f;

#define ISSUE_STAGE(s, kb)                                                  \
    do {                                                                    \
        uint32_t ab = sbase + (s) * (STG_W * 4);                            \
        uint32_t bb = ab + 128 * AS_LD * 4;                                 \
        _Pragma("unroll")                                                   \
        for (int l = 0; l < 4; ++l) {                                       \
            int id = l * 256 + tid;                                         \
            int ar = id >> 3, ac = (id & 7) << 2;                           \
            cpa16(ab + (uint32_t)(ar * AS_LD + ac) * 4,                     \
                  A + (size_t)(bm + ar) * K + (kb) + ac);                   \
            int br = id >> 5, bc = (id & 31) << 2;                          \
            cpa16(bb + (uint32_t)(br * BS_LD + bc) * 4,                     \
                  Bm + (size_t)((kb) + br) * N + bn + bc);                  \
        }                                                                   \
    } while (0)

    ISSUE_STAGE(0, 0);
    cpa_commit();
    ISSUE_STAGE(1, 32);
    cpa_commit();

    for (int i = 0; i < nslab; ++i) {
        if (i + 1 < nslab) cpa_wait<1>(); else cpa_wait<0>();
        __syncthreads();
        if (i + 2 < nslab) {
            ISSUE_STAGE((i + 2) % 3, (i + 2) << 5);
            cpa_commit();
        }

        const uint32_t* a_s = sm + (i % 3) * STG_W;
        const uint32_t* b_s = a_s + 128 * AS_LD;

#pragma unroll
        for (int ks = 0; ks < 32; ks += 8) {
            uint32_t af[4][4], bf[4][2];
#pragma unroll
            for (int mt = 0; mt < 4; ++mt) {
                int m0 = wm + mt * 16;
                af[mt][0] = a_s[(m0 + g)     * AS_LD + ks + tg];
                af[mt][1] = a_s[(m0 + g + 8) * AS_LD + ks + tg];
                af[mt][2] = a_s[(m0 + g)     * AS_LD + ks + tg + 4];
                af[mt][3] = a_s[(m0 + g + 8) * AS_LD + ks + tg + 4];
            }
#pragma unroll
            for (int nt = 0; nt < 4; ++nt) {
                int n0 = wn + nt * 8;
                bf[nt][0] = b_s[(ks + tg)     * BS_LD + n0 + g];
                bf[nt][1] = b_s[(ks + tg + 4) * BS_LD + n0 + g];
            }
#pragma unroll
            for (int mt = 0; mt < 4; ++mt)
#pragma unroll
                for (int nt = 0; nt < 4; ++nt)
                    mma_tf32(acc[mt][nt], af[mt], bf[nt]);
        }
        __syncthreads();
    }

    // epilogue
    float* Cout;
    int ldc, coff;
    if (SPLIT) {
        if (bn < 2048)      { Cout = g_q; ldc = 2048; coff = bn; }
        else if (bn < 2560) { Cout = g_k; ldc = 512;  coff = bn - 2048; }
        else                { Cout = g_v; ldc = 512;  coff = bn - 2560; }
    } else {
        Cout = C0; ldc = N; coff = bn;
    }

#pragma unroll
    for (int mt = 0; mt < 4; ++mt) {
#pragma unroll
        for (int nt = 0; nt < 4; ++nt) {
            int r0  = bm + wm + mt * 16 + g;
            int col = coff + wn + nt * 8 + tg * 2;
            float2 lo, hi;
            if (SPLIT) {
                lo = make_float2(tf32f(acc[mt][nt][0]), tf32f(acc[mt][nt][1]));
                hi = make_float2(tf32f(acc[mt][nt][2]), tf32f(acc[mt][nt][3]));
            } else {
                lo = make_float2(acc[mt][nt][0], acc[mt][nt][1]);
                hi = make_float2(acc[mt][nt][2], acc[mt][nt][3]);
            }
            *(float2*)(Cout + (size_t)r0 * ldc + col)       = lo;
            *(float2*)(Cout + (size_t)(r0 + 8) * ldc + col) = hi;
        }
    }
}

// ---------------- RoPE: rotate, fold softmax scale into q, round to tf32 ---
__global__ void rope_kernel(float* __restrict__ q, float* __restrict__ k) {
    const int NH = H_ + KV_;
    int idx = blockIdx.x * blockDim.x + threadIdx.x;
    const int total = M_TOK * NH * (D_ / 2);
    if (idx >= total) return;

    int p   = idx & 31;
    int hh  = (idx >> 5) % NH;
    int tok = idx / (32 * NH);
    int tseq = tok & (T_ - 1);

    float inv = powf(10000.0f, -(float)p / 32.0f);
    float ang = (float)tseq * inv;
    float s, c;
    sincosf(ang, &s, &c);

    const float SCq = 0.125f * 1.4426950408889634f;  // 1/sqrt(D) * log2(e)

    float* base;
    float scale;
    if (hh < H_) { base = q + (size_t)tok * C_ + hh * D_;            scale = SCq; }
    else         { base = k + (size_t)tok * KVDIM + (hh - H_) * D_;  scale = 1.0f; }
    float e0 = base[2 * p];
    float e1 = base[2 * p + 1];
    base[2 * p]     = tf32f((e0 * c - e1 * s) * scale);
    base[2 * p + 1] = tf32f((e1 * c + e0 * s) * scale);
}

// ---------------- flash attention v2 (tf32 mma, cp.async, shuffle-P) -------
// 128 threads / 4 warps, BQ=64 (16 rows/warp), BK=64, double-buffered K/V.
// All inputs pre-rounded tf32 (q also pre-scaled); no cvt in the loop.
#define FLD 68
#define FWORDS (64 * FLD)
#define SMEM_F (4 * FWORDS * 4)   // K[2] + V[2] = 69632 B

__global__ void __launch_bounds__(128, 3)
flash_tc(const float* __restrict__ Q, const float* __restrict__ K,
         const float* __restrict__ V, float* __restrict__ O) {
    extern __shared__ uint32_t fsm[];
    // words: K stage s at s*FWORDS; V stage s at (2+s)*FWORDS; Q staged in V1.
    const uint32_t sbase = smem_u32(fsm);

    const int tid  = threadIdx.x;
    const int warp = tid >> 5;
    const int lane = tid & 31;
    const int g    = lane >> 2;
    const int tg   = lane & 3;

    const int qi = blockIdx.x;
    const int bh = blockIdx.y;
    const int b  = bh >> 5;
    const int h  = bh & 31;
    const int hk = h >> 2;
    const int q0 = qi * 64;
    const int qrow = warp * 16;
    const int bT = b * T_;

#define ISSUE_KV(j, s)                                                      \
    do {                                                                    \
        uint32_t kb = sbase + (s) * (FWORDS * 4);                           \
        uint32_t vb = sbase + (2 + (s)) * (FWORDS * 4);                     \
        int k0i = (j) * 64;                                                 \
        _Pragma("unroll")                                                   \
        for (int l = 0; l < 8; ++l) {                                       \
            int id = l * 128 + tid;                                         \
            int r = id >> 4, c = (id & 15) << 2;                            \
            const float* src = K + (size_t)(bT + k0i + r) * KVDIM +         \
                               hk * D_ + c;                                 \
            cpa16(kb + (uint32_t)(r * FLD + c) * 4, src);                   \
        }                                                                   \
        _Pragma("unroll")                                                   \
        for (int l = 0; l < 8; ++l) {                                       \
            int id = l * 128 + tid;                                         \
            int r = id >> 4, c = (id & 15) << 2;                            \
            const float* src = V + (size_t)(bT + k0i + r) * KVDIM +         \
                               hk * D_ + c;                                 \
            cpa16(vb + (uint32_t)(r * FLD + c) * 4, src);                   \
        }                                                                   \
    } while (0)

    // --- prologue: Q -> V-stage-1 region; KV tile 0 -> stage 0 ---
    {
        uint32_t qb = sbase + 3 * (FWORDS * 4);
#pragma unroll
        for (int l = 0; l < 8; ++l) {
            int id = l * 128 + tid;
            int r = id >> 4, c = (id & 15) << 2;
            cpa16(qb + (uint32_t)(r * FLD + c) * 4,
                  Q + (size_t)(bT + q0 + r) * C_ + h * D_ + c);
        }
        cpa_commit();
    }
    ISSUE_KV(0, 0);
    cpa_commit();

    cpa_wait<1>();       // Q done (KV0 may still be in flight)
    __syncthreads();

    uint32_t qf[8][4];
    {
        const uint32_t* Qs = fsm + 3 * FWORDS;
#pragma unroll
        for (int ks = 0; ks < 8; ++ks) {
            qf[ks][0] = Qs[(qrow + g)     * FLD + ks * 8 + tg];
            qf[ks][1] = Qs[(qrow + g + 8) * FLD + ks * 8 + tg];
            qf[ks][2] = Qs[(qrow + g)     * FLD + ks * 8 + tg + 4];
            qf[ks][3] = Qs[(qrow + g + 8) * FLD + ks * 8 + tg + 4];
        }
    }
    __syncthreads();     // everyone extracted Q before stage-1 overwrite

    if (qi >= 1) {
        ISSUE_KV(1, 1);
        cpa_commit();
    }

    float m1 = -INFINITY, m2 = -INFINITY, l1 = 0.0f, l2 = 0.0f;
    float oacc[8][4];
#pragma unroll
    for (int nt = 0; nt < 8; ++nt)
#pragma unroll
        for (int c = 0; c < 4; ++c) oacc[nt][c] = 0.0f;

    const int srcA = (lane & 28) | (tg >> 1);
    const int srcB = srcA + 2;
    const bool odd = tg & 1;

    for (int j = 0; j <= qi; ++j) {
        if (j < qi) cpa_wait<1>(); else cpa_wait<0>();
        __syncthreads();

        const uint32_t* Ks = fsm + (j & 1) * FWORDS;
        const uint32_t* Vs = fsm + (2 + (j & 1)) * FWORDS;
        const int k0 = j * 64;

        // S = Q K^T (16x64 per warp), already in exp2 domain
        float sacc[8][4];
#pragma unroll
        for (int nt = 0; nt < 8; ++nt)
#pragma unroll
            for (int c = 0; c < 4; ++c) sacc[nt][c] = 0.0f;

#pragma unroll
        for (int nt = 0; nt < 8; ++nt) {
#pragma unroll
            for (int ks = 0; ks < 8; ++ks) {
                uint32_t bf[2];
                bf[0] = Ks[(nt * 8 + g) * FLD + ks * 8 + tg];
                bf[1] = Ks[(nt * 8 + g) * FLD + ks * 8 + tg + 4];
                mma_tf32(sacc[nt], qf[ks], bf);
            }
        }

        if (j == qi) {
            int r1 = q0 + qrow + g, r2 = r1 + 8;
#pragma unroll
            for (int nt = 0; nt < 8; ++nt) {
                int c0 = k0 + nt * 8 + tg * 2;
                if (c0     > r1) sacc[nt][0] = -INFINITY;
                if (c0 + 1 > r1) sacc[nt][1] = -INFINITY;
                if (c0     > r2) sacc[nt][2] = -INFINITY;
                if (c0 + 1 > r2) sacc[nt][3] = -INFINITY;
            }
        }

        float a1 = -INFINITY, a2 = -INFINITY;
#pragma unroll
        for (int nt = 0; nt < 8; ++nt) {
            a1 = fmaxf(a1, fmaxf(sacc[nt][0], sacc[nt][1]));
            a2 = fmaxf(a2, fmaxf(sacc[nt][2], sacc[nt][3]));
        }
        a1 = fmaxf(a1, __shfl_xor_sync(0xffffffff, a1, 1));
        a1 = fmaxf(a1, __shfl_xor_sync(0xffffffff, a1, 2));
        a2 = fmaxf(a2, __shfl_xor_sync(0xffffffff, a2, 1));
        a2 = fmaxf(a2, __shfl_xor_sync(0xffffffff, a2, 2));

        float mn1 = fmaxf(m1, a1), mn2 = fmaxf(m2, a2);
        float al1 = ex2f(m1 - mn1), al2 = ex2f(m2 - mn2);

        float s1 = 0.0f, s2 = 0.0f;
#pragma unroll
        for (int nt = 0; nt < 8; ++nt) {
            sacc[nt][0] = ex2f(sacc[nt][0] - mn1);
            sacc[nt][1] = ex2f(sacc[nt][1] - mn1);
            sacc[nt][2] = ex2f(sacc[nt][2] - mn2);
            sacc[nt][3] = ex2f(sacc[nt][3] - mn2);
            s1 += sacc[nt][0] + sacc[nt][1];
            s2 += sacc[nt][2] + sacc[nt][3];
        }
        s1 += __shfl_xor_sync(0xffffffff, s1, 1);
        s1 += __shfl_xor_sync(0xffffffff, s1, 2);
        s2 += __shfl_xor_sync(0xffffffff, s2, 1);
        s2 += __shfl_xor_sync(0xffffffff, s2, 2);

        l1 = l1 * al1 + s1;
        l2 = l2 * al2 + s2;
        m1 = mn1;
        m2 = mn2;

#pragma unroll
        for (int nt = 0; nt < 8; ++nt) {
            oacc[nt][0] *= al1; oacc[nt][1] *= al1;
            oacc[nt][2] *= al2; oacc[nt][3] *= al2;
        }

        // O += P V : P C-frag -> A-frag via shuffles (chunk ks uses tile ks)
#pragma unroll
        for (int ks = 0; ks < 8; ++ks) {
            float v0 = __shfl_sync(0xffffffff, sacc[ks][0], srcA);
            float v1 = __shfl_sync(0xffffffff, sacc[ks][1], srcA);
            float v2 = __shfl_sync(0xffffffff, sacc[ks][2], srcA);
            float v3 = __shfl_sync(0xffffffff, sacc[ks][3], srcA);
            float w0 = __shfl_sync(0xffffffff, sacc[ks][0], srcB);
            float w1 = __shfl_sync(0xffffffff, sacc[ks][1], srcB);
            float w2 = __shfl_sync(0xffffffff, sacc[ks][2], srcB);
            float w3 = __shfl_sync(0xffffffff, sacc[ks][3], srcB);
            uint32_t af[4];
            af[0] = to_tf32(odd ? v1 : v0);   // (g,     ks*8+tg)
            af[1] = to_tf32(odd ? v3 : v2);   // (g+8,   ks*8+tg)
            af[2] = to_tf32(odd ? w1 : w0);   // (g,     ks*8+tg+4)
            af[3] = to_tf32(odd ? w3 : w2);   // (g+8,   ks*8+tg+4)
#pragma unroll
            for (int nt = 0; nt < 8; ++nt) {
                uint32_t bf[2];
                bf[0] = Vs[(ks * 8 + tg)     * FLD + nt * 8 + g];
                bf[1] = Vs[(ks * 8 + tg + 4) * FLD + nt * 8 + g];
                mma_tf32(oacc[nt], af, bf);
            }
        }

        __syncthreads();   // compute done before stage (j&1) is overwritten
        if (j + 2 <= qi) {
            ISSUE_KV(j + 2, j & 1);
            cpa_commit();
        }
    }

    // epilogue: normalize, round to tf32 (out-proj input), write [tok, H*D]
    float i1 = 1.0f / l1, i2 = 1.0f / l2;
    int r1 = q0 + qrow + g, r2 = r1 + 8;
#pragma unroll
    for (int nt = 0; nt < 8; ++nt) {
        int col = h * D_ + nt * 8 + tg * 2;
        float2 lo = make_float2(tf32f(oacc[nt][0] * i1), tf32f(oacc[nt][1] * i1));
        float2 hi = make_float2(tf32f(oacc[nt][2] * i2), tf32f(oacc[nt][3] * i2));
        *(float2*)(O + (size_t)(bT + r1) * C_ + col) = lo;
        *(float2*)(O + (size_t)(bT + r2) * C_ + col) = hi;
    }
}

// ---------------------------------------------------------------------------
extern "C" void kernel_launch(void* const* d_in, const int* in_sizes, int n_in,
                              void* d_out, int out_size) {
    const float* x  = (const float*)d_in[0];
    const float* Wq = (const float*)d_in[1];
    const float* Wk = (const float*)d_in[2];
    const float* Wv = (const float*)d_in[3];
    const float* Wp = (const float*)d_in[4];
    float* out = (float*)d_out;

    float *q, *k, *v, *att, *xc, *wqkv, *wpc;
    cudaGetSymbolAddress((void**)&q,    g_q);
    cudaGetSymbolAddress((void**)&k,    g_k);
    cudaGetSymbolAddress((void**)&v,    g_v);
    cudaGetSymbolAddress((void**)&att,  g_att);
    cudaGetSymbolAddress((void**)&xc,   g_xc);
    cudaGetSymbolAddress((void**)&wqkv, g_wqkv);
    cudaGetSymbolAddress((void**)&wpc,  g_wpc);

    cudaFuncSetAttribute(gemm_cp<1>,
                         cudaFuncAttributeMaxDynamicSharedMemorySize, SMEM_G);
    cudaFuncSetAttribute(gemm_cp<0>,
                         cudaFuncAttributeMaxDynamicSharedMemorySize, SMEM_G);
    cudaFuncSetAttribute(flash_tc,
                         cudaFuncAttributeMaxDynamicSharedMemorySize, SMEM_F);

    // 1. tf32 pre-conversion + weight packing
    cvt_pack<<<(M_TOK * C_ / 4 + 255) / 256, 256>>>(x, Wq, Wk, Wv, Wp);

    // 2. fused QKV projection (writes g_q/g_k/g_v, tf32-rounded)
    gemm_cp<1><<<dim3(NQKV / 128, M_TOK / 128), 256, SMEM_G>>>(
        xc, wqkv, q, M_TOK, NQKV, C_);

    // 3. RoPE (q gets softmax scale folded in; outputs tf32-rounded)
    int total_pairs = M_TOK * (H_ + KV_) * (D_ / 2);
    rope_kernel<<<(total_pairs + 255) / 256, 256>>>(q, k);

    // 4. causal flash attention with GQA
    flash_tc<<<dim3(T_ / 64, B_ * H_), 128, SMEM_F>>>(q, k, v, att);

    // 5. output projection
    gemm_cp<0><<<dim3(C_ / 128, M_TOK / 128), 256, SMEM_G>>>(
        att, wpc, out, M_TOK, C_, C_);
}

// round 7
// speedup vs baseline: 3.7593x; 1.0002x over previous
#include <cuda_runtime.h>
#include <math.h>
#include <stdint.h>

#define B_    4
#define T_    1024
#define C_    2048
#define H_    32
#define KV_   8
#define D_    64
#define M_TOK 4096
#define KVDIM 512
#define NQKV  3072          // 2048 q + 512 k + 512 v

// ---------------- scratch (device globals; no allocation allowed) ----------
__device__ float g_q[M_TOK * C_];        // 32 MB
__device__ float g_k[M_TOK * KVDIM];     //  8 MB
__device__ float g_v[M_TOK * KVDIM];     //  8 MB
__device__ float g_att[M_TOK * C_];      // 32 MB
__device__ float g_xc[M_TOK * C_];       // 32 MB  tf32(x)
__device__ float g_wqkv[C_ * NQKV];      // 24 MB  tf32([Wq|Wk|Wv]) [k][n]
__device__ float g_wpc[C_ * C_];         // 16 MB  tf32(Wp)

// ------------------------- helpers -----------------------------------------
__device__ __forceinline__ uint32_t to_tf32(float x) {
    uint32_t r;
    asm("cvt.rna.tf32.f32 %0, %1;" : "=r"(r) : "f"(x));
    return r;
}
__device__ __forceinline__ float tf32f(float x) {
    return __uint_as_float(to_tf32(x));
}
__device__ __forceinline__ float ex2f(float x) {
    float r;
    asm("ex2.approx.f32 %0, %1;" : "=f"(r) : "f"(x));
    return r;
}
__device__ __forceinline__ void mma_tf32(float c[4], const uint32_t a[4],
                                         const uint32_t b[2]) {
    asm volatile(
        "mma.sync.aligned.m16n8k8.row.col.f32.tf32.tf32.f32 "
        "{%0,%1,%2,%3}, {%4,%5,%6,%7}, {%8,%9}, {%0,%1,%2,%3};"
        : "+f"(c[0]), "+f"(c[1]), "+f"(c[2]), "+f"(c[3])
        : "r"(a[0]), "r"(a[1]), "r"(a[2]), "r"(a[3]), "r"(b[0]), "r"(b[1]));
}
__device__ __forceinline__ uint32_t smem_u32(const void* p) {
    uint32_t a;
    asm("{ .reg .u64 t; cvta.to.shared.u64 t, %1; cvt.u32.u64 %0, t; }"
        : "=r"(a) : "l"(p));
    return a;
}
__device__ __forceinline__ void cpa16(uint32_t dst, const void* src) {
    asm volatile("cp.async.cg.shared.global [%0], [%1], 16;"
                 :: "r"(dst), "l"(src) : "memory");
}
__device__ __forceinline__ void cpa_commit() {
    asm volatile("cp.async.commit_group;" ::: "memory");
}
template <int N> __device__ __forceinline__ void cpa_wait() {
    asm volatile("cp.async.wait_group %0;" :: "n"(N) : "memory");
}

// ---------------- tf32 pre-conversion / weight packing ---------------------
__global__ void cvt_pack(const float* __restrict__ x,
                         const float* __restrict__ Wq,
                         const float* __restrict__ Wk,
                         const float* __restrict__ Wv,
                         const float* __restrict__ Wp) {
    int i4 = blockIdx.x * blockDim.x + threadIdx.x;

    if (i4 < M_TOK * C_ / 4) {
        float4 v = ((const float4*)x)[i4];
        v.x = tf32f(v.x); v.y = tf32f(v.y); v.z = tf32f(v.z); v.w = tf32f(v.w);
        ((float4*)g_xc)[i4] = v;
    }
    if (i4 < C_ * C_ / 4) {
        float4 v = ((const float4*)Wp)[i4];
        v.x = tf32f(v.x); v.y = tf32f(v.y); v.z = tf32f(v.z); v.w = tf32f(v.w);
        ((float4*)g_wpc)[i4] = v;
    }
    if (i4 < C_ * NQKV / 4) {
        int k = i4 / (NQKV / 4);
        int n = (i4 % (NQKV / 4)) * 4;
        const float* src = (n < 2048) ? Wq + (size_t)k * 2048 + n
                         : (n < 2560) ? Wk + (size_t)k * 512 + (n - 2048)
                                      : Wv + (size_t)k * 512 + (n - 2560);
        float4 v = *(const float4*)src;
        v.x = tf32f(v.x); v.y = tf32f(v.y); v.z = tf32f(v.z); v.w = tf32f(v.w);
        ((float4*)g_wqkv)[i4] = v;
    }
}

// ============ cp.async 3-stage tf32 GEMM: C[M,N] = A[M,K] @ B[K,N] =========
// 128x128x32 tile, 8 warps (2x4), warp tile 64x32, m16n8k8.
// Inputs already tf32-valued f32 -> no cvt in mainloop.
#define AS_LD 36
#define BS_LD 132
#define STG_W (128 * AS_LD + 32 * BS_LD)   // 8832 words/stage
#define SMEM_G (3 * STG_W * 4)             // 105984 B

template <int SPLIT>
__global__ void __launch_bounds__(256)
gemm_cp(const float* __restrict__ A, const float* __restrict__ Bm,
        float* __restrict__ C0, int M, int N, int K) {
    extern __shared__ uint32_t sm[];

    const int tid  = threadIdx.x;
    const int bm   = blockIdx.y * 128;
    const int bn   = blockIdx.x * 128;
    const int warp = tid >> 5;
    const int lane = tid & 31;
    const int g    = lane >> 2;
    const int tg   = lane & 3;
    const int wm   = (warp >> 2) * 64;
    const int wn   = (warp & 3) * 32;
    const int nslab = K >> 5;

    const uint32_t sbase = smem_u32(sm);

    float acc[4][4][4];
#pragma unroll
    for (int i = 0; i < 4; ++i)
#pragma unroll
        for (int j = 0; j < 4; ++j)
#pragma unroll
            for (int c = 0; c < 4; ++c) acc[i][j][c] = 0.0f;

#define ISSUE_STAGE(s, kb)                                                  \
    do {                                                                    \
        uint32_t ab = sbase + (s) * (STG_W * 4);                            \
        uint32_t bb = ab + 128 * AS_LD * 4;                                 \
        _Pragma("unroll")                                                   \
        for (int l = 0; l < 4; ++l) {                                       \
            int id = l * 256 + tid;                                         \
            int ar = id >> 3, ac = (id & 7) << 2;                           \
            cpa16(ab + (uint32_t)(ar * AS_LD + ac) * 4,                     \
                  A + (size_t)(bm + ar) * K + (kb) + ac);                   \
            int br = id >> 5, bc = (id & 31) << 2;                          \
            cpa16(bb + (uint32_t)(br * BS_LD + bc) * 4,                     \
                  Bm + (size_t)((kb) + br) * N + bn + bc);                  \
        }                                                                   \
    } while (0)

    ISSUE_STAGE(0, 0);
    cpa_commit();
    ISSUE_STAGE(1, 32);
    cpa_commit();

    for (int i = 0; i < nslab; ++i) {
        if (i + 1 < nslab) cpa_wait<1>(); else cpa_wait<0>();
        __syncthreads();
        if (i + 2 < nslab) {
            ISSUE_STAGE((i + 2) % 3, (i + 2) << 5);
            cpa_commit();
        }

        const uint32_t* a_s = sm + (i % 3) * STG_W;
        const uint32_t* b_s = a_s + 128 * AS_LD;

#pragma unroll
        for (int ks = 0; ks < 32; ks += 8) {
            uint32_t af[4][4], bf[4][2];
#pragma unroll
            for (int mt = 0; mt < 4; ++mt) {
                int m0 = wm + mt * 16;
                af[mt][0] = a_s[(m0 + g)     * AS_LD + ks + tg];
                af[mt][1] = a_s[(m0 + g + 8) * AS_LD + ks + tg];
                af[mt][2] = a_s[(m0 + g)     * AS_LD + ks + tg + 4];
                af[mt][3] = a_s[(m0 + g + 8) * AS_LD + ks + tg + 4];
            }
#pragma unroll
            for (int nt = 0; nt < 4; ++nt) {
                int n0 = wn + nt * 8;
                bf[nt][0] = b_s[(ks + tg)     * BS_LD + n0 + g];
                bf[nt][1] = b_s[(ks + tg + 4) * BS_LD + n0 + g];
            }
#pragma unroll
            for (int mt = 0; mt < 4; ++mt)
#pragma unroll
                for (int nt = 0; nt < 4; ++nt)
                    mma_tf32(acc[mt][nt], af[mt], bf[nt]);
        }
        __syncthreads();
    }

    // epilogue
    float* Cout;
    int ldc, coff;
    if (SPLIT) {
        if (bn < 2048)      { Cout = g_q; ldc = 2048; coff = bn; }
        else if (bn < 2560) { Cout = g_k; ldc = 512;  coff = bn - 2048; }
        else                { Cout = g_v; ldc = 512;  coff = bn - 2560; }
    } else {
        Cout = C0; ldc = N; coff = bn;
    }

#pragma unroll
    for (int mt = 0; mt < 4; ++mt) {
#pragma unroll
        for (int nt = 0; nt < 4; ++nt) {
            int r0  = bm + wm + mt * 16 + g;
            int col = coff + wn + nt * 8 + tg * 2;
            float2 lo, hi;
            if (SPLIT) {
                lo = make_float2(tf32f(acc[mt][nt][0]), tf32f(acc[mt][nt][1]));
                hi = make_float2(tf32f(acc[mt][nt][2]), tf32f(acc[mt][nt][3]));
            } else {
                lo = make_float2(acc[mt][nt][0], acc[mt][nt][1]);
                hi = make_float2(acc[mt][nt][2], acc[mt][nt][3]);
            }
            *(float2*)(Cout + (size_t)r0 * ldc + col)       = lo;
            *(float2*)(Cout + (size_t)(r0 + 8) * ldc + col) = hi;
        }
    }
}

// ---------------- RoPE: rotate, fold softmax scale into q, round to tf32 ---
__global__ void rope_kernel(float* __restrict__ q, float* __restrict__ k) {
    const int NH = H_ + KV_;
    int idx = blockIdx.x * blockDim.x + threadIdx.x;
    const int total = M_TOK * NH * (D_ / 2);
    if (idx >= total) return;

    int p   = idx & 31;
    int hh  = (idx >> 5) % NH;
    int tok = idx / (32 * NH);
    int tseq = tok & (T_ - 1);

    float inv = powf(10000.0f, -(float)p / 32.0f);
    float ang = (float)tseq * inv;
    float s, c;
    sincosf(ang, &s, &c);

    const float SCq = 0.125f * 1.4426950408889634f;  // 1/sqrt(D) * log2(e)

    float* base;
    float scale;
    if (hh < H_) { base = q + (size_t)tok * C_ + hh * D_;            scale = SCq; }
    else         { base = k + (size_t)tok * KVDIM + (hh - H_) * D_;  scale = 1.0f; }
    float e0 = base[2 * p];
    float e1 = base[2 * p + 1];
    base[2 * p]     = tf32f((e0 * c - e1 * s) * scale);
    base[2 * p + 1] = tf32f((e1 * c + e0 * s) * scale);
}

// ---------------- flash attention v2 (tf32 mma, cp.async, shuffle-P) -------
// 128 threads / 4 warps, BQ=64 (16 rows/warp), BK=64, double-buffered K/V.
// All inputs pre-rounded tf32 (q also pre-scaled); no cvt in the loop.
#define FLD 68
#define FWORDS (64 * FLD)
#define SMEM_F (4 * FWORDS * 4)   // K[2] + V[2] = 69632 B

__global__ void __launch_bounds__(128, 3)
flash_tc(const float* __restrict__ Q, const float* __restrict__ K,
         const float* __restrict__ V, float* __restrict__ O) {
    extern __shared__ uint32_t fsm[];
    // words: K stage s at s*FWORDS; V stage s at (2+s)*FWORDS; Q staged in V1.
    const uint32_t sbase = smem_u32(fsm);

    const int tid  = threadIdx.x;
    const int warp = tid >> 5;
    const int lane = tid & 31;
    const int g    = lane >> 2;
    const int tg   = lane & 3;

    const int qi = blockIdx.x;
    const int bh = blockIdx.y;
    const int b  = bh >> 5;
    const int h  = bh & 31;
    const int hk = h >> 2;
    const int q0 = qi * 64;
    const int qrow = warp * 16;
    const int bT = b * T_;

#define ISSUE_KV(j, s)                                                      \
    do {                                                                    \
        uint32_t kb = sbase + (s) * (FWORDS * 4);                           \
        uint32_t vb = sbase + (2 + (s)) * (FWORDS * 4);                     \
        int k0i = (j) * 64;                                                 \
        _Pragma("unroll")                                                   \
        for (int l = 0; l < 8; ++l) {                                       \
            int id = l * 128 + tid;                                         \
            int r = id >> 4, c = (id & 15) << 2;                            \
            const float* src = K + (size_t)(bT + k0i + r) * KVDIM +         \
                               hk * D_ + c;                                 \
            cpa16(kb + (uint32_t)(r * FLD + c) * 4, src);                   \
        }                                                                   \
        _Pragma("unroll")                                                   \
        for (int l = 0; l < 8; ++l) {                                       \
            int id = l * 128 + tid;                                         \
            int r = id >> 4, c = (id & 15) << 2;                            \
            const float* src = V + (size_t)(bT + k0i + r) * KVDIM +         \
                               hk * D_ + c;                                 \
            cpa16(vb + (uint32_t)(r * FLD + c) * 4, src);                   \
        }                                                                   \
    } while (0)

    // --- prologue: Q -> V-stage-1 region; KV tile 0 -> stage 0 ---
    {
        uint32_t qb = sbase + 3 * (FWORDS * 4);
#pragma unroll
        for (int l = 0; l < 8; ++l) {
            int id = l * 128 + tid;
            int r = id >> 4, c = (id & 15) << 2;
            cpa16(qb + (uint32_t)(r * FLD + c) * 4,
                  Q + (size_t)(bT + q0 + r) * C_ + h * D_ + c);
        }
        cpa_commit();
    }
    ISSUE_KV(0, 0);
    cpa_commit();

    cpa_wait<1>();       // Q done (KV0 may still be in flight)
    __syncthreads();

    uint32_t qf[8][4];
    {
        const uint32_t* Qs = fsm + 3 * FWORDS;
#pragma unroll
        for (int ks = 0; ks < 8; ++ks) {
            qf[ks][0] = Qs[(qrow + g)     * FLD + ks * 8 + tg];
            qf[ks][1] = Qs[(qrow + g + 8) * FLD + ks * 8 + tg];
            qf[ks][2] = Qs[(qrow + g)     * FLD + ks * 8 + tg + 4];
            qf[ks][3] = Qs[(qrow + g + 8) * FLD + ks * 8 + tg + 4];
        }
    }
    __syncthreads();     // everyone extracted Q before stage-1 overwrite

    if (qi >= 1) {
        ISSUE_KV(1, 1);
        cpa_commit();
    }

    float m1 = -INFINITY, m2 = -INFINITY, l1 = 0.0f, l2 = 0.0f;
    float oacc[8][4];
#pragma unroll
    for (int nt = 0; nt < 8; ++nt)
#pragma unroll
        for (int c = 0; c < 4; ++c) oacc[nt][c] = 0.0f;

    const int srcA = (lane & 28) | (tg >> 1);
    const int srcB = srcA + 2;
    const bool odd = tg & 1;

    for (int j = 0; j <= qi; ++j) {
        if (j < qi) cpa_wait<1>(); else cpa_wait<0>();
        __syncthreads();

        const uint32_t* Ks = fsm + (j & 1) * FWORDS;
        const uint32_t* Vs = fsm + (2 + (j & 1)) * FWORDS;
        const int k0 = j * 64;

        // S = Q K^T (16x64 per warp), already in exp2 domain
        float sacc[8][4];
#pragma unroll
        for (int nt = 0; nt < 8; ++nt)
#pragma unroll
            for (int c = 0; c < 4; ++c) sacc[nt][c] = 0.0f;

#pragma unroll
        for (int nt = 0; nt < 8; ++nt) {
#pragma unroll
            for (int ks = 0; ks < 8; ++ks) {
                uint32_t bf[2];
                bf[0] = Ks[(nt * 8 + g) * FLD + ks * 8 + tg];
                bf[1] = Ks[(nt * 8 + g) * FLD + ks * 8 + tg + 4];
                mma_tf32(sacc[nt], qf[ks], bf);
            }
        }

        if (j == qi) {
            int r1 = q0 + qrow + g, r2 = r1 + 8;
#pragma unroll
            for (int nt = 0; nt < 8; ++nt) {
                int c0 = k0 + nt * 8 + tg * 2;
                if (c0     > r1) sacc[nt][0] = -INFINITY;
                if (c0 + 1 > r1) sacc[nt][1] = -INFINITY;
                if (c0     > r2) sacc[nt][2] = -INFINITY;
                if (c0 + 1 > r2) sacc[nt][3] = -INFINITY;
            }
        }

        float a1 = -INFINITY, a2 = -INFINITY;
#pragma unroll
        for (int nt = 0; nt < 8; ++nt) {
            a1 = fmaxf(a1, fmaxf(sacc[nt][0], sacc[nt][1]));
            a2 = fmaxf(a2, fmaxf(sacc[nt][2], sacc[nt][3]));
        }
        a1 = fmaxf(a1, __shfl_xor_sync(0xffffffff, a1, 1));
        a1 = fmaxf(a1, __shfl_xor_sync(0xffffffff, a1, 2));
        a2 = fmaxf(a2, __shfl_xor_sync(0xffffffff, a2, 1));
        a2 = fmaxf(a2, __shfl_xor_sync(0xffffffff, a2, 2));

        float mn1 = fmaxf(m1, a1), mn2 = fmaxf(m2, a2);
        float al1 = ex2f(m1 - mn1), al2 = ex2f(m2 - mn2);

        float s1 = 0.0f, s2 = 0.0f;
#pragma unroll
        for (int nt = 0; nt < 8; ++nt) {
            sacc[nt][0] = ex2f(sacc[nt][0] - mn1);
            sacc[nt][1] = ex2f(sacc[nt][1] - mn1);
            sacc[nt][2] = ex2f(sacc[nt][2] - mn2);
            sacc[nt][3] = ex2f(sacc[nt][3] - mn2);
            s1 += sacc[nt][0] + sacc[nt][1];
            s2 += sacc[nt][2] + sacc[nt][3];
        }
        s1 += __shfl_xor_sync(0xffffffff, s1, 1);
        s1 += __shfl_xor_sync(0xffffffff, s1, 2);
        s2 += __shfl_xor_sync(0xffffffff, s2, 1);
        s2 += __shfl_xor_sync(0xffffffff, s2, 2);

        l1 = l1 * al1 + s1;
        l2 = l2 * al2 + s2;
        m1 = mn1;
        m2 = mn2;

#pragma unroll
        for (int nt = 0; nt < 8; ++nt) {
            oacc[nt][0] *= al1; oacc[nt][1] *= al1;
            oacc[nt][2] *= al2; oacc[nt][3] *= al2;
        }

        // O += P V : P C-frag -> A-frag via shuffles (chunk ks uses tile ks)
#pragma unroll
        for (int ks = 0; ks < 8; ++ks) {
            float v0 = __shfl_sync(0xffffffff, sacc[ks][0], srcA);
            float v1 = __shfl_sync(0xffffffff, sacc[ks][1], srcA);
            float v2 = __shfl_sync(0xffffffff, sacc[ks][2], srcA);
            float v3 = __shfl_sync(0xffffffff, sacc[ks][3], srcA);
            float w0 = __shfl_sync(0xffffffff, sacc[ks][0], srcB);
            float w1 = __shfl_sync(0xffffffff, sacc[ks][1], srcB);
            float w2 = __shfl_sync(0xffffffff, sacc[ks][2], srcB);
            float w3 = __shfl_sync(0xffffffff, sacc[ks][3], srcB);
            uint32_t af[4];
            af[0] = to_tf32(odd ? v1 : v0);   // (g,     ks*8+tg)
            af[1] = to_tf32(odd ? v3 : v2);   // (g+8,   ks*8+tg)
            af[2] = to_tf32(odd ? w1 : w0);   // (g,     ks*8+tg+4)
            af[3] = to_tf32(odd ? w3 : w2);   // (g+8,   ks*8+tg+4)
#pragma unroll
            for (int nt = 0; nt < 8; ++nt) {
                uint32_t bf[2];
                bf[0] = Vs[(ks * 8 + tg)     * FLD + nt * 8 + g];
                bf[1] = Vs[(ks * 8 + tg + 4) * FLD + nt * 8 + g];
                mma_tf32(oacc[nt], af, bf);
            }
        }

        __syncthreads();   // compute done before stage (j&1) is overwritten
        if (j + 2 <= qi) {
            ISSUE_KV(j + 2, j & 1);
            cpa_commit();
        }
    }

    // epilogue: normalize, round to tf32 (out-proj input), write [tok, H*D]
    float i1 = 1.0f / l1, i2 = 1.0f / l2;
    int r1 = q0 + qrow + g, r2 = r1 + 8;
#pragma unroll
    for (int nt = 0; nt < 8; ++nt) {
        int col = h * D_ + nt * 8 + tg * 2;
        float2 lo = make_float2(tf32f(oacc[nt][0] * i1), tf32f(oacc[nt][1] * i1));
        float2 hi = make_float2(tf32f(oacc[nt][2] * i2), tf32f(oacc[nt][3] * i2));
        *(float2*)(O + (size_t)(bT + r1) * C_ + col) = lo;
        *(float2*)(O + (size_t)(bT + r2) * C_ + col) = hi;
    }
}

// ---------------------------------------------------------------------------
extern "C" void kernel_launch(void* const* d_in, const int* in_sizes, int n_in,
                              void* d_out, int out_size) {
    const float* x  = (const float*)d_in[0];
    const float* Wq = (const float*)d_in[1];
    const float* Wk = (const float*)d_in[2];
    const float* Wv = (const float*)d_in[3];
    const float* Wp = (const float*)d_in[4];
    float* out = (float*)d_out;

    float *q, *k, *v, *att, *xc, *wqkv, *wpc;
    cudaGetSymbolAddress((void**)&q,    g_q);
    cudaGetSymbolAddress((void**)&k,    g_k);
    cudaGetSymbolAddress((void**)&v,    g_v);
    cudaGetSymbolAddress((void**)&att,  g_att);
    cudaGetSymbolAddress((void**)&xc,   g_xc);
    cudaGetSymbolAddress((void**)&wqkv, g_wqkv);
    cudaGetSymbolAddress((void**)&wpc,  g_wpc);

    cudaFuncSetAttribute(gemm_cp<1>,
                         cudaFuncAttributeMaxDynamicSharedMemorySize, SMEM_G);
    cudaFuncSetAttribute(gemm_cp<0>,
                         cudaFuncAttributeMaxDynamicSharedMemorySize, SMEM_G);
    cudaFuncSetAttribute(flash_tc,
                         cudaFuncAttributeMaxDynamicSharedMemorySize, SMEM_F);

    // 1. tf32 pre-conversion + weight packing
    cvt_pack<<<(M_TOK * C_ / 4 + 255) / 256, 256>>>(x, Wq, Wk, Wv, Wp);

    // 2. fused QKV projection (writes g_q/g_k/g_v, tf32-rounded)
    gemm_cp<1><<<dim3(NQKV / 128, M_TOK / 128), 256, SMEM_G>>>(
        xc, wqkv, q, M_TOK, NQKV, C_);

    // 3. RoPE (q gets softmax scale folded in; outputs tf32-rounded)
    int total_pairs = M_TOK * (H_ + KV_) * (D_ / 2);
    rope_kernel<<<(total_pairs + 255) / 256, 256>>>(q, k);

    // 4. causal flash attention with GQA
    flash_tc<<<dim3(T_ / 64, B_ * H_), 128, SMEM_F>>>(q, k, v, att);

    // 5. output projection
    gemm_cp<0><<<dim3(C_ / 128, M_TOK / 128), 256, SMEM_G>>>(
        att, wpc, out, M_TOK, C_, C_);
}

// round 8
// speedup vs baseline: 5.5598x; 1.4789x over previous
#include <cuda_runtime.h>
#include <cuda_fp16.h>
#include <math.h>
#include <stdint.h>

#define B_    4
#define T_    1024
#define C_    2048
#define H_    32
#define KV_   8
#define D_    64
#define M_TOK 4096
#define KVDIM 512
#define NQKV  3072          // 2048 q + 512 k + 512 v

// ---------------- scratch (device globals; no allocation allowed) ----------
__device__ float  g_q[M_TOK * C_];          // 32 MB fp32 (tf32-valued)
__device__ float  g_k[M_TOK * KVDIM];       //  8 MB
__device__ float  g_v[M_TOK * KVDIM];       //  8 MB
__device__ __half g_xh[M_TOK * C_];         // 16 MB  fp16(x)       [m][k]
__device__ __half g_wqkvh[C_ * NQKV];       // 12 MB  fp16 weights  [k/2][n][2]
__device__ __half g_wph[C_ * C_];           //  8 MB  fp16(Wp)      [k/2][n][2]
__device__ __half g_atth[M_TOK * C_];       // 16 MB  fp16 attention out

// ------------------------- helpers -----------------------------------------
__device__ __forceinline__ uint32_t to_tf32(float x) {
    uint32_t r;
    asm("cvt.rna.tf32.f32 %0, %1;" : "=r"(r) : "f"(x));
    return r;
}
__device__ __forceinline__ float tf32f(float x) {
    return __uint_as_float(to_tf32(x));
}
__device__ __forceinline__ float ex2f(float x) {
    float r;
    asm("ex2.approx.f32 %0, %1;" : "=f"(r) : "f"(x));
    return r;
}
__device__ __forceinline__ void mma_tf32(float c[4], const uint32_t a[4],
                                         const uint32_t b[2]) {
    asm volatile(
        "mma.sync.aligned.m16n8k8.row.col.f32.tf32.tf32.f32 "
        "{%0,%1,%2,%3}, {%4,%5,%6,%7}, {%8,%9}, {%0,%1,%2,%3};"
        : "+f"(c[0]), "+f"(c[1]), "+f"(c[2]), "+f"(c[3])
        : "r"(a[0]), "r"(a[1]), "r"(a[2]), "r"(a[3]), "r"(b[0]), "r"(b[1]));
}
__device__ __forceinline__ void mma_f16(float c[4], const uint32_t a[4],
                                        const uint32_t b[2]) {
    asm volatile(
        "mma.sync.aligned.m16n8k16.row.col.f32.f16.f16.f32 "
        "{%0,%1,%2,%3}, {%4,%5,%6,%7}, {%8,%9}, {%0,%1,%2,%3};"
        : "+f"(c[0]), "+f"(c[1]), "+f"(c[2]), "+f"(c[3])
        : "r"(a[0]), "r"(a[1]), "r"(a[2]), "r"(a[3]), "r"(b[0]), "r"(b[1]));
}
__device__ __forceinline__ uint32_t smem_u32(const void* p) {
    uint32_t a;
    asm("{ .reg .u64 t; cvta.to.shared.u64 t, %1; cvt.u32.u64 %0, t; }"
        : "=r"(a) : "l"(p));
    return a;
}
__device__ __forceinline__ void cpa16(uint32_t dst, const void* src) {
    asm volatile("cp.async.cg.shared.global [%0], [%1], 16;"
                 :: "r"(dst), "l"(src) : "memory");
}
__device__ __forceinline__ void cpa_commit() {
    asm volatile("cp.async.commit_group;" ::: "memory");
}
template <int N> __device__ __forceinline__ void cpa_wait() {
    asm volatile("cp.async.wait_group %0;" :: "n"(N) : "memory");
}

// ---------------- fp16 pre-conversion / weight interleave ------------------
// Weights go to [k/2][n][2] "k-pair interleaved" so the mma B fragment
// (n, k=2t,2t+1) is one contiguous .b32.
__global__ void cvt_pack(const float* __restrict__ x,
                         const float* __restrict__ Wq,
                         const float* __restrict__ Wk,
                         const float* __restrict__ Wv,
                         const float* __restrict__ Wp) {
    int i4 = blockIdx.x * blockDim.x + threadIdx.x;

    if (i4 < M_TOK * C_ / 4) {
        float4 v = ((const float4*)x)[i4];
        __half2* dst = (__half2*)(g_xh) + i4 * 2;
        dst[0] = __floats2half2_rn(v.x, v.y);
        dst[1] = __floats2half2_rn(v.z, v.w);
    }
    if (i4 < (C_ / 2) * (NQKV / 4)) {
        int r = i4 / (NQKV / 4);
        int n = (i4 % (NQKV / 4)) * 4;
        int k0 = 2 * r;
        const float *s0, *s1;
        if (n < 2048)      { s0 = Wq + (size_t)k0 * 2048 + n;
                             s1 = Wq + (size_t)(k0 + 1) * 2048 + n; }
        else if (n < 2560) { s0 = Wk + (size_t)k0 * 512 + (n - 2048);
                             s1 = Wk + (size_t)(k0 + 1) * 512 + (n - 2048); }
        else               { s0 = Wv + (size_t)k0 * 512 + (n - 2560);
                             s1 = Wv + (size_t)(k0 + 1) * 512 + (n - 2560); }
        float4 a = *(const float4*)s0;
        float4 b = *(const float4*)s1;
        __half2* dst = (__half2*)(g_wqkvh + (size_t)r * 2 * NQKV + n * 2);
        dst[0] = __floats2half2_rn(a.x, b.x);
        dst[1] = __floats2half2_rn(a.y, b.y);
        dst[2] = __floats2half2_rn(a.z, b.z);
        dst[3] = __floats2half2_rn(a.w, b.w);
    }
    if (i4 < (C_ / 2) * (C_ / 4)) {
        int r = i4 / (C_ / 4);
        int n = (i4 % (C_ / 4)) * 4;
        float4 a = *(const float4*)(Wp + (size_t)(2 * r) * C_ + n);
        float4 b = *(const float4*)(Wp + (size_t)(2 * r + 1) * C_ + n);
        __half2* dst = (__half2*)(g_wph + (size_t)r * 2 * C_ + n * 2);
        dst[0] = __floats2half2_rn(a.x, b.x);
        dst[1] = __floats2half2_rn(a.y, b.y);
        dst[2] = __floats2half2_rn(a.z, b.z);
        dst[3] = __floats2half2_rn(a.w, b.w);
    }
}

// ============ fp16 cp.async 3-stage GEMM: C[M,N] = A[M,K] @ B[K,N] =========
// 128x128x32 tile, 8 warps (2x4), warp tile 64x32, m16n8k16, f32 accum.
// A smem: [128][AW] words (half2 per word, [m][k]); B smem: [16][BW] words
// ([kpair][n]). AW=20 / BW=136 padding -> conflict-free fragment LDS.
#define AW 20
#define BW 136
#define A_WORDS (128 * AW)    // 2560
#define B_WORDS (16 * BW)     // 2176
#define STG_W (A_WORDS + B_WORDS)
#define SMEM_G (3 * STG_W * 4)

template <int SPLIT>
__global__ void __launch_bounds__(256)
gemm_hp(const __half* __restrict__ A, const __half* __restrict__ Bm,
        float* __restrict__ C0, int M, int N, int K) {
    extern __shared__ uint32_t sm[];

    const int tid  = threadIdx.x;
    const int bm   = blockIdx.y * 128;
    const int bn   = blockIdx.x * 128;
    const int warp = tid >> 5;
    const int lane = tid & 31;
    const int g    = lane >> 2;
    const int tg   = lane & 3;
    const int wm   = (warp >> 2) * 64;
    const int wn   = (warp & 3) * 32;
    const int nslab = K >> 5;

    const uint32_t sbase = smem_u32(sm);

    float acc[4][4][4];
#pragma unroll
    for (int i = 0; i < 4; ++i)
#pragma unroll
        for (int j = 0; j < 4; ++j)
#pragma unroll
            for (int c = 0; c < 4; ++c) acc[i][j][c] = 0.0f;

#define ISSUE_STAGE(s, kb)                                                  \
    do {                                                                    \
        uint32_t ab = sbase + (s) * (STG_W * 4);                            \
        uint32_t bb = ab + A_WORDS * 4;                                     \
        _Pragma("unroll")                                                   \
        for (int l = 0; l < 2; ++l) {                                       \
            int c = l * 256 + tid;                                          \
            int row = c >> 2, wo = (c & 3) * 4;                             \
            cpa16(ab + (uint32_t)(row * AW + wo) * 4,                       \
                  A + (size_t)(bm + row) * K + (kb) + wo * 2);              \
        }                                                                   \
        _Pragma("unroll")                                                   \
        for (int l = 0; l < 2; ++l) {                                       \
            int c = l * 256 + tid;                                          \
            int r = c >> 5, nw = (c & 31) * 4;                              \
            cpa16(bb + (uint32_t)(r * BW + nw) * 4,                         \
                  Bm + ((size_t)((kb) >> 1) + r) * (2 * N) +                \
                      (size_t)(bn + nw) * 2);                               \
        }                                                                   \
    } while (0)

    ISSUE_STAGE(0, 0);
    cpa_commit();
    ISSUE_STAGE(1, 32);
    cpa_commit();

    for (int i = 0; i < nslab; ++i) {
        if (i + 1 < nslab) cpa_wait<1>(); else cpa_wait<0>();
        __syncthreads();
        if (i + 2 < nslab) {
            ISSUE_STAGE((i + 2) % 3, (i + 2) << 5);
            cpa_commit();
        }

        const uint32_t* a_s = sm + (i % 3) * STG_W;
        const uint32_t* b_s = a_s + A_WORDS;

#pragma unroll
        for (int ks = 0; ks < 2; ++ks) {        // two k16 chunks
            const int kp = ks * 8;
            uint32_t af[4][4], bf[4][2];
#pragma unroll
            for (int mt = 0; mt < 4; ++mt) {
                int m0 = wm + mt * 16;
                af[mt][0] = a_s[(m0 + g)     * AW + kp + tg];
                af[mt][1] = a_s[(m0 + g + 8) * AW + kp + tg];
                af[mt][2] = a_s[(m0 + g)     * AW + kp + tg + 4];
                af[mt][3] = a_s[(m0 + g + 8) * AW + kp + tg + 4];
            }
#pragma unroll
            for (int nt = 0; nt < 4; ++nt) {
                int n0 = wn + nt * 8;
                bf[nt][0] = b_s[(kp + tg)     * BW + n0 + g];
                bf[nt][1] = b_s[(kp + tg + 4) * BW + n0 + g];
            }
#pragma unroll
            for (int mt = 0; mt < 4; ++mt)
#pragma unroll
                for (int nt = 0; nt < 4; ++nt)
                    mma_f16(acc[mt][nt], af[mt], bf[nt]);
        }
        __syncthreads();
    }

    // epilogue
    float* Cout;
    int ldc, coff;
    if (SPLIT) {
        if (bn < 2048)      { Cout = g_q; ldc = 2048; coff = bn; }
        else if (bn < 2560) { Cout = g_k; ldc = 512;  coff = bn - 2048; }
        else                { Cout = g_v; ldc = 512;  coff = bn - 2560; }
    } else {
        Cout = C0; ldc = N; coff = bn;
    }

#pragma unroll
    for (int mt = 0; mt < 4; ++mt) {
#pragma unroll
        for (int nt = 0; nt < 4; ++nt) {
            int r0  = bm + wm + mt * 16 + g;
            int col = coff + wn + nt * 8 + tg * 2;
            float2 lo, hi;
            if (SPLIT) {
                lo = make_float2(tf32f(acc[mt][nt][0]), tf32f(acc[mt][nt][1]));
                hi = make_float2(tf32f(acc[mt][nt][2]), tf32f(acc[mt][nt][3]));
            } else {
                lo = make_float2(acc[mt][nt][0], acc[mt][nt][1]);
                hi = make_float2(acc[mt][nt][2], acc[mt][nt][3]);
            }
            *(float2*)(Cout + (size_t)r0 * ldc + col)       = lo;
            *(float2*)(Cout + (size_t)(r0 + 8) * ldc + col) = hi;
        }
    }
}

// ---------------- RoPE: rotate, fold softmax scale into q, round to tf32 ---
__global__ void rope_kernel(float* __restrict__ q, float* __restrict__ k) {
    const int NH = H_ + KV_;
    int idx = blockIdx.x * blockDim.x + threadIdx.x;
    const int total = M_TOK * NH * (D_ / 2);
    if (idx >= total) return;

    int p   = idx & 31;
    int hh  = (idx >> 5) % NH;
    int tok = idx / (32 * NH);
    int tseq = tok & (T_ - 1);

    float inv = powf(10000.0f, -(float)p / 32.0f);
    float ang = (float)tseq * inv;
    float s, c;
    sincosf(ang, &s, &c);

    const float SCq = 0.125f * 1.4426950408889634f;

    float* base;
    float scale;
    if (hh < H_) { base = q + (size_t)tok * C_ + hh * D_;            scale = SCq; }
    else         { base = k + (size_t)tok * KVDIM + (hh - H_) * D_;  scale = 1.0f; }
    float e0 = base[2 * p];
    float e1 = base[2 * p + 1];
    base[2 * p]     = tf32f((e0 * c - e1 * s) * scale);
    base[2 * p + 1] = tf32f((e1 * c + e0 * s) * scale);
}

// ---------------- flash attention (tf32 mma, cp.async, shuffle-P) ----------
// Unchanged from R7 except the epilogue writes fp16 att for the out-proj.
#define FLD 68
#define FWORDS (64 * FLD)
#define SMEM_F (4 * FWORDS * 4)

__global__ void __launch_bounds__(128, 3)
flash_tc(const float* __restrict__ Q, const float* __restrict__ K,
         const float* __restrict__ V, __half* __restrict__ O) {
    extern __shared__ uint32_t fsm[];
    const uint32_t sbase = smem_u32(fsm);

    const int tid  = threadIdx.x;
    const int warp = tid >> 5;
    const int lane = tid & 31;
    const int g    = lane >> 2;
    const int tg   = lane & 3;

    const int qi = blockIdx.x;
    const int bh = blockIdx.y;
    const int b  = bh >> 5;
    const int h  = bh & 31;
    const int hk = h >> 2;
    const int q0 = qi * 64;
    const int qrow = warp * 16;
    const int bT = b * T_;

#define ISSUE_KV(j, s)                                                      \
    do {                                                                    \
        uint32_t kb = sbase + (s) * (FWORDS * 4);                           \
        uint32_t vb = sbase + (2 + (s)) * (FWORDS * 4);                     \
        int k0i = (j) * 64;                                                 \
        _Pragma("unroll")                                                   \
        for (int l = 0; l < 8; ++l) {                                       \
            int id = l * 128 + tid;                                         \
            int r = id >> 4, c = (id & 15) << 2;                            \
            cpa16(kb + (uint32_t)(r * FLD + c) * 4,                         \
                  K + (size_t)(bT + k0i + r) * KVDIM + hk * D_ + c);        \
        }                                                                   \
        _Pragma("unroll")                                                   \
        for (int l = 0; l < 8; ++l) {                                       \
            int id = l * 128 + tid;                                         \
            int r = id >> 4, c = (id & 15) << 2;                            \
            cpa16(vb + (uint32_t)(r * FLD + c) * 4,                         \
                  V + (size_t)(bT + k0i + r) * KVDIM + hk * D_ + c);        \
        }                                                                   \
    } while (0)

    {
        uint32_t qb = sbase + 3 * (FWORDS * 4);
#pragma unroll
        for (int l = 0; l < 8; ++l) {
            int id = l * 128 + tid;
            int r = id >> 4, c = (id & 15) << 2;
            cpa16(qb + (uint32_t)(r * FLD + c) * 4,
                  Q + (size_t)(bT + q0 + r) * C_ + h * D_ + c);
        }
        cpa_commit();
    }
    ISSUE_KV(0, 0);
    cpa_commit();

    cpa_wait<1>();
    __syncthreads();

    uint32_t qf[8][4];
    {
        const uint32_t* Qs = fsm + 3 * FWORDS;
#pragma unroll
        for (int ks = 0; ks < 8; ++ks) {
            qf[ks][0] = Qs[(qrow + g)     * FLD + ks * 8 + tg];
            qf[ks][1] = Qs[(qrow + g + 8) * FLD + ks * 8 + tg];
            qf[ks][2] = Qs[(qrow + g)     * FLD + ks * 8 + tg + 4];
            qf[ks][3] = Qs[(qrow + g + 8) * FLD + ks * 8 + tg + 4];
        }
    }
    __syncthreads();

    if (qi >= 1) {
        ISSUE_KV(1, 1);
        cpa_commit();
    }

    float m1 = -INFINITY, m2 = -INFINITY, l1 = 0.0f, l2 = 0.0f;
    float oacc[8][4];
#pragma unroll
    for (int nt = 0; nt < 8; ++nt)
#pragma unroll
        for (int c = 0; c < 4; ++c) oacc[nt][c] = 0.0f;

    const int srcA = (lane & 28) | (tg >> 1);
    const int srcB = srcA + 2;
    const bool odd = tg & 1;

    for (int j = 0; j <= qi; ++j) {
        if (j < qi) cpa_wait<1>(); else cpa_wait<0>();
        __syncthreads();

        const uint32_t* Ks = fsm + (j & 1) * FWORDS;
        const uint32_t* Vs = fsm + (2 + (j & 1)) * FWORDS;
        const int k0 = j * 64;

        float sacc[8][4];
#pragma unroll
        for (int nt = 0; nt < 8; ++nt)
#pragma unroll
            for (int c = 0; c < 4; ++c) sacc[nt][c] = 0.0f;

#pragma unroll
        for (int nt = 0; nt < 8; ++nt) {
#pragma unroll
            for (int ks = 0; ks < 8; ++ks) {
                uint32_t bf[2];
                bf[0] = Ks[(nt * 8 + g) * FLD + ks * 8 + tg];
                bf[1] = Ks[(nt * 8 + g) * FLD + ks * 8 + tg + 4];
                mma_tf32(sacc[nt], qf[ks], bf);
            }
        }

        if (j == qi) {
            int r1 = q0 + qrow + g, r2 = r1 + 8;
#pragma unroll
            for (int nt = 0; nt < 8; ++nt) {
                int c0 = k0 + nt * 8 + tg * 2;
                if (c0     > r1) sacc[nt][0] = -INFINITY;
                if (c0 + 1 > r1) sacc[nt][1] = -INFINITY;
                if (c0     > r2) sacc[nt][2] = -INFINITY;
                if (c0 + 1 > r2) sacc[nt][3] = -INFINITY;
            }
        }

        float a1 = -INFINITY, a2 = -INFINITY;
#pragma unroll
        for (int nt = 0; nt < 8; ++nt) {
            a1 = fmaxf(a1, fmaxf(sacc[nt][0], sacc[nt][1]));
            a2 = fmaxf(a2, fmaxf(sacc[nt][2], sacc[nt][3]));
        }
        a1 = fmaxf(a1, __shfl_xor_sync(0xffffffff, a1, 1));
        a1 = fmaxf(a1, __shfl_xor_sync(0xffffffff, a1, 2));
        a2 = fmaxf(a2, __shfl_xor_sync(0xffffffff, a2, 1));
        a2 = fmaxf(a2, __shfl_xor_sync(0xffffffff, a2, 2));

        float mn1 = fmaxf(m1, a1), mn2 = fmaxf(m2, a2);
        float al1 = ex2f(m1 - mn1), al2 = ex2f(m2 - mn2);

        float s1 = 0.0f, s2 = 0.0f;
#pragma unroll
        for (int nt = 0; nt < 8; ++nt) {
            sacc[nt][0] = ex2f(sacc[nt][0] - mn1);
            sacc[nt][1] = ex2f(sacc[nt][1] - mn1);
            sacc[nt][2] = ex2f(sacc[nt][2] - mn2);
            sacc[nt][3] = ex2f(sacc[nt][3] - mn2);
            s1 += sacc[nt][0] + sacc[nt][1];
            s2 += sacc[nt][2] + sacc[nt][3];
        }
        s1 += __shfl_xor_sync(0xffffffff, s1, 1);
        s1 += __shfl_xor_sync(0xffffffff, s1, 2);
        s2 += __shfl_xor_sync(0xffffffff, s2, 1);
        s2 += __shfl_xor_sync(0xffffffff, s2, 2);

        l1 = l1 * al1 + s1;
        l2 = l2 * al2 + s2;
        m1 = mn1;
        m2 = mn2;

#pragma unroll
        for (int nt = 0; nt < 8; ++nt) {
            oacc[nt][0] *= al1; oacc[nt][1] *= al1;
            oacc[nt][2] *= al2; oacc[nt][3] *= al2;
        }

#pragma unroll
        for (int ks = 0; ks < 8; ++ks) {
            float v0 = __shfl_sync(0xffffffff, sacc[ks][0], srcA);
            float v1 = __shfl_sync(0xffffffff, sacc[ks][1], srcA);
            float v2 = __shfl_sync(0xffffffff, sacc[ks][2], srcA);
            float v3 = __shfl_sync(0xffffffff, sacc[ks][3], srcA);
            float w0 = __shfl_sync(0xffffffff, sacc[ks][0], srcB);
            float w1 = __shfl_sync(0xffffffff, sacc[ks][1], srcB);
            float w2 = __shfl_sync(0xffffffff, sacc[ks][2], srcB);
            float w3 = __shfl_sync(0xffffffff, sacc[ks][3], srcB);
            uint32_t af[4];
            af[0] = to_tf32(odd ? v1 : v0);
            af[1] = to_tf32(odd ? v3 : v2);
            af[2] = to_tf32(odd ? w1 : w0);
            af[3] = to_tf32(odd ? w3 : w2);
#pragma unroll
            for (int nt = 0; nt < 8; ++nt) {
                uint32_t bf[2];
                bf[0] = Vs[(ks * 8 + tg)     * FLD + nt * 8 + g];
                bf[1] = Vs[(ks * 8 + tg + 4) * FLD + nt * 8 + g];
                mma_tf32(oacc[nt], af, bf);
            }
        }

        __syncthreads();
        if (j + 2 <= qi) {
            ISSUE_KV(j + 2, j & 1);
            cpa_commit();
        }
    }

    // epilogue: normalize, write fp16 att [tok, H*D]
    float i1 = 1.0f / l1, i2 = 1.0f / l2;
    int r1 = q0 + qrow + g, r2 = r1 + 8;
#pragma unroll
    for (int nt = 0; nt < 8; ++nt) {
        int col = h * D_ + nt * 8 + tg * 2;
        __half2 lo = __floats2half2_rn(oacc[nt][0] * i1, oacc[nt][1] * i1);
        __half2 hi = __floats2half2_rn(oacc[nt][2] * i2, oacc[nt][3] * i2);
        *(__half2*)(O + (size_t)(bT + r1) * C_ + col) = lo;
        *(__half2*)(O + (size_t)(bT + r2) * C_ + col) = hi;
    }
}

// ---------------------------------------------------------------------------
extern "C" void kernel_launch(void* const* d_in, const int* in_sizes, int n_in,
                              void* d_out, int out_size) {
    const float* x  = (const float*)d_in[0];
    const float* Wq = (const float*)d_in[1];
    const float* Wk = (const float*)d_in[2];
    const float* Wv = (const float*)d_in[3];
    const float* Wp = (const float*)d_in[4];
    float* out = (float*)d_out;

    float *q, *k, *v;
    __half *xh, *wqkvh, *wph, *atth;
    cudaGetSymbolAddress((void**)&q,     g_q);
    cudaGetSymbolAddress((void**)&k,     g_k);
    cudaGetSymbolAddress((void**)&v,     g_v);
    cudaGetSymbolAddress((void**)&xh,    g_xh);
    cudaGetSymbolAddress((void**)&wqkvh, g_wqkvh);
    cudaGetSymbolAddress((void**)&wph,   g_wph);
    cudaGetSymbolAddress((void**)&atth,  g_atth);

    cudaFuncSetAttribute(gemm_hp<1>,
                         cudaFuncAttributeMaxDynamicSharedMemorySize, SMEM_G);
    cudaFuncSetAttribute(gemm_hp<0>,
                         cudaFuncAttributeMaxDynamicSharedMemorySize, SMEM_G);
    cudaFuncSetAttribute(flash_tc,
                         cudaFuncAttributeMaxDynamicSharedMemorySize, SMEM_F);

    // 1. fp16 pre-conversion + weight interleave
    cvt_pack<<<(M_TOK * C_ / 4 + 255) / 256, 256>>>(x, Wq, Wk, Wv, Wp);

    // 2. fused QKV projection (fp16 mma, writes fp32 tf32-rounded q/k/v)
    gemm_hp<1><<<dim3(NQKV / 128, M_TOK / 128), 256, SMEM_G>>>(
        xh, wqkvh, q, M_TOK, NQKV, C_);

    // 3. RoPE
    int total_pairs = M_TOK * (H_ + KV_) * (D_ / 2);
    rope_kernel<<<(total_pairs + 255) / 256, 256>>>(q, k);

    // 4. causal flash attention with GQA (tf32 mma, fp16 output)
    flash_tc<<<dim3(T_ / 64, B_ * H_), 128, SMEM_F>>>(q, k, v, atth);

    // 5. output projection (fp16 mma)
    gemm_hp<0><<<dim3(C_ / 128, M_TOK / 128), 256, SMEM_G>>>(
        atth, wph, out, M_TOK, C_, C_);
}

// round 9
// speedup vs baseline: 6.5984x; 1.1868x over previous
#include <cuda_runtime.h>
#include <cuda_fp16.h>
#include <math.h>
#include <stdint.h>

#define B_    4
#define T_    1024
#define C_    2048
#define H_    32
#define KV_   8
#define D_    64
#define M_TOK 4096
#define KVDIM 512
#define NQKV  3072          // 2048 q + 512 k + 512 v

// ---------------- scratch (device globals; no allocation allowed) ----------
__device__ float  g_q[M_TOK * C_];          // fp32 q pre-rope
__device__ float  g_k[M_TOK * KVDIM];       // fp32 k pre-rope
__device__ __half g_qh[M_TOK * C_];         // fp16 q post-rope (scaled)
__device__ __half g_kh[M_TOK * KVDIM];      // fp16 k post-rope
__device__ __half g_vp[M_TOK * KVDIM];      // fp16 v, [tok/2][dk][2] packed
__device__ __half g_xh[M_TOK * C_];         // fp16(x)       [m][k]
__device__ __half g_wqkvh[C_ * NQKV];       // fp16 weights  [k/2][n][2]
__device__ __half g_wph[C_ * C_];           // fp16(Wp)      [k/2][n][2]
__device__ __half g_atth[M_TOK * C_];       // fp16 attention out

// ------------------------- helpers -----------------------------------------
__device__ __forceinline__ float ex2f(float x) {
    float r;
    asm("ex2.approx.f32 %0, %1;" : "=f"(r) : "f"(x));
    return r;
}
__device__ __forceinline__ uint32_t packh2(float a, float b) {
    __half2 h = __floats2half2_rn(a, b);
    return *(uint32_t*)&h;
}
__device__ __forceinline__ void mma_f16(float c[4], const uint32_t a[4],
                                        const uint32_t b[2]) {
    asm volatile(
        "mma.sync.aligned.m16n8k16.row.col.f32.f16.f16.f32 "
        "{%0,%1,%2,%3}, {%4,%5,%6,%7}, {%8,%9}, {%0,%1,%2,%3};"
        : "+f"(c[0]), "+f"(c[1]), "+f"(c[2]), "+f"(c[3])
        : "r"(a[0]), "r"(a[1]), "r"(a[2]), "r"(a[3]), "r"(b[0]), "r"(b[1]));
}
__device__ __forceinline__ uint32_t smem_u32(const void* p) {
    uint32_t a;
    asm("{ .reg .u64 t; cvta.to.shared.u64 t, %1; cvt.u32.u64 %0, t; }"
        : "=r"(a) : "l"(p));
    return a;
}
__device__ __forceinline__ void cpa16(uint32_t dst, const void* src) {
    asm volatile("cp.async.cg.shared.global [%0], [%1], 16;"
                 :: "r"(dst), "l"(src) : "memory");
}
__device__ __forceinline__ void cpa_commit() {
    asm volatile("cp.async.commit_group;" ::: "memory");
}
template <int N> __device__ __forceinline__ void cpa_wait() {
    asm volatile("cp.async.wait_group %0;" :: "n"(N) : "memory");
}

// ---------------- fp16 pre-conversion / weight interleave ------------------
__global__ void cvt_pack(const float* __restrict__ x,
                         const float* __restrict__ Wq,
                         const float* __restrict__ Wk,
                         const float* __restrict__ Wv,
                         const float* __restrict__ Wp) {
    int i4 = blockIdx.x * blockDim.x + threadIdx.x;

    if (i4 < M_TOK * C_ / 4) {
        float4 v = ((const float4*)x)[i4];
        __half2* dst = (__half2*)(g_xh) + i4 * 2;
        dst[0] = __floats2half2_rn(v.x, v.y);
        dst[1] = __floats2half2_rn(v.z, v.w);
    }
    if (i4 < (C_ / 2) * (NQKV / 4)) {
        int r = i4 / (NQKV / 4);
        int n = (i4 % (NQKV / 4)) * 4;
        int k0 = 2 * r;
        const float *s0, *s1;
        if (n < 2048)      { s0 = Wq + (size_t)k0 * 2048 + n;
                             s1 = Wq + (size_t)(k0 + 1) * 2048 + n; }
        else if (n < 2560) { s0 = Wk + (size_t)k0 * 512 + (n - 2048);
                             s1 = Wk + (size_t)(k0 + 1) * 512 + (n - 2048); }
        else               { s0 = Wv + (size_t)k0 * 512 + (n - 2560);
                             s1 = Wv + (size_t)(k0 + 1) * 512 + (n - 2560); }
        float4 a = *(const float4*)s0;
        float4 b = *(const float4*)s1;
        __half2* dst = (__half2*)(g_wqkvh + (size_t)r * 2 * NQKV + n * 2);
        dst[0] = __floats2half2_rn(a.x, b.x);
        dst[1] = __floats2half2_rn(a.y, b.y);
        dst[2] = __floats2half2_rn(a.z, b.z);
        dst[3] = __floats2half2_rn(a.w, b.w);
    }
    if (i4 < (C_ / 2) * (C_ / 4)) {
        int r = i4 / (C_ / 4);
        int n = (i4 % (C_ / 4)) * 4;
        float4 a = *(const float4*)(Wp + (size_t)(2 * r) * C_ + n);
        float4 b = *(const float4*)(Wp + (size_t)(2 * r + 1) * C_ + n);
        __half2* dst = (__half2*)(g_wph + (size_t)r * 2 * C_ + n * 2);
        dst[0] = __floats2half2_rn(a.x, b.x);
        dst[1] = __floats2half2_rn(a.y, b.y);
        dst[2] = __floats2half2_rn(a.z, b.z);
        dst[3] = __floats2half2_rn(a.w, b.w);
    }
}

// ============ fp16 cp.async 3-stage GEMM: C[M,N] = A[M,K] @ B[K,N] =========
#define AW 20
#define BW 136
#define A_WORDS (128 * AW)
#define B_WORDS (16 * BW)
#define STG_W (A_WORDS + B_WORDS)
#define SMEM_G (3 * STG_W * 4)
#define CW 68     // V repack: half2 words per row (64 + 4 pad)

template <int SPLIT>
__global__ void __launch_bounds__(256)
gemm_hp(const __half* __restrict__ A, const __half* __restrict__ Bm,
        float* __restrict__ C0, int M, int N, int K) {
    extern __shared__ uint32_t sm[];

    const int tid  = threadIdx.x;
    const int bm   = blockIdx.y * 128;
    const int bn   = blockIdx.x * 128;
    const int warp = tid >> 5;
    const int lane = tid & 31;
    const int g    = lane >> 2;
    const int tg   = lane & 3;
    const int wm   = (warp >> 2) * 64;
    const int wn   = (warp & 3) * 32;
    const int nslab = K >> 5;

    const uint32_t sbase = smem_u32(sm);

    float acc[4][4][4];
#pragma unroll
    for (int i = 0; i < 4; ++i)
#pragma unroll
        for (int j = 0; j < 4; ++j)
#pragma unroll
            for (int c = 0; c < 4; ++c) acc[i][j][c] = 0.0f;

#define ISSUE_STAGE(s, kb)                                                  \
    do {                                                                    \
        uint32_t ab = sbase + (s) * (STG_W * 4);                            \
        uint32_t bb = ab + A_WORDS * 4;                                     \
        _Pragma("unroll")                                                   \
        for (int l = 0; l < 2; ++l) {                                       \
            int c = l * 256 + tid;                                          \
            int row = c >> 2, wo = (c & 3) * 4;                             \
            cpa16(ab + (uint32_t)(row * AW + wo) * 4,                       \
                  A + (size_t)(bm + row) * K + (kb) + wo * 2);              \
        }                                                                   \
        _Pragma("unroll")                                                   \
        for (int l = 0; l < 2; ++l) {                                       \
            int c = l * 256 + tid;                                          \
            int r = c >> 5, nw = (c & 31) * 4;                              \
            cpa16(bb + (uint32_t)(r * BW + nw) * 4,                         \
                  Bm + ((size_t)((kb) >> 1) + r) * (2 * N) +                \
                      (size_t)(bn + nw) * 2);                               \
        }                                                                   \
    } while (0)

    ISSUE_STAGE(0, 0);
    cpa_commit();
    ISSUE_STAGE(1, 32);
    cpa_commit();

    for (int i = 0; i < nslab; ++i) {
        if (i + 1 < nslab) cpa_wait<1>(); else cpa_wait<0>();
        __syncthreads();
        if (i + 2 < nslab) {
            ISSUE_STAGE((i + 2) % 3, (i + 2) << 5);
            cpa_commit();
        }

        const uint32_t* a_s = sm + (i % 3) * STG_W;
        const uint32_t* b_s = a_s + A_WORDS;

#pragma unroll
        for (int ks = 0; ks < 2; ++ks) {
            const int kp = ks * 8;
            uint32_t af[4][4], bf[4][2];
#pragma unroll
            for (int mt = 0; mt < 4; ++mt) {
                int m0 = wm + mt * 16;
                af[mt][0] = a_s[(m0 + g)     * AW + kp + tg];
                af[mt][1] = a_s[(m0 + g + 8) * AW + kp + tg];
                af[mt][2] = a_s[(m0 + g)     * AW + kp + tg + 4];
                af[mt][3] = a_s[(m0 + g + 8) * AW + kp + tg + 4];
            }
#pragma unroll
            for (int nt = 0; nt < 4; ++nt) {
                int n0 = wn + nt * 8;
                bf[nt][0] = b_s[(kp + tg)     * BW + n0 + g];
                bf[nt][1] = b_s[(kp + tg + 4) * BW + n0 + g];
            }
#pragma unroll
            for (int mt = 0; mt < 4; ++mt)
#pragma unroll
                for (int nt = 0; nt < 4; ++nt)
                    mma_f16(acc[mt][nt], af[mt], bf[nt]);
        }
        __syncthreads();
    }

    if (SPLIT && bn >= 2560) {
        // ---- V tile: repack through smem into [tok/2][dk][2] fp16 ----
        // store fp16 C tile to smem [128][CW] half2-words
#pragma unroll
        for (int mt = 0; mt < 4; ++mt)
#pragma unroll
            for (int nt = 0; nt < 4; ++nt) {
                int r0 = wm + mt * 16 + g;
                int cw = (wn + nt * 8 + tg * 2) >> 1;
                sm[r0 * CW + cw]       = packh2(acc[mt][nt][0], acc[mt][nt][1]);
                sm[(r0 + 8) * CW + cw] = packh2(acc[mt][nt][2], acc[mt][nt][3]);
            }
        __syncthreads();
        // repack: out word addr = (bm/2 + tp)*512 + (bn-2560) + 2*cw
        uint32_t* vp32 = (uint32_t*)g_vp;
#pragma unroll
        for (int it = 0; it < 16; ++it) {
            int id = it * 256 + tid;
            int tp = id >> 6, cw = id & 63;
            uint32_t a = sm[(2 * tp) * CW + cw];
            uint32_t b = sm[(2 * tp + 1) * CW + cw];
            __half2 ah = *(__half2*)&a, bh = *(__half2*)&b;
            uint2 o;
            o.x = packh2(__low2float(ah),  __low2float(bh));
            o.y = packh2(__high2float(ah), __high2float(bh));
            *(uint2*)(vp32 + ((size_t)(bm >> 1) + tp) * 512 +
                      (bn - 2560) + 2 * cw) = o;
        }
        return;
    }

    // ---- q/k (fp32 for rope) or plain fp32 output ----
    float* Cout;
    int ldc, coff;
    if (SPLIT) {
        if (bn < 2048) { Cout = g_q; ldc = 2048; coff = bn; }
        else           { Cout = g_k; ldc = 512;  coff = bn - 2048; }
    } else {
        Cout = C0; ldc = N; coff = bn;
    }

#pragma unroll
    for (int mt = 0; mt < 4; ++mt) {
#pragma unroll
        for (int nt = 0; nt < 4; ++nt) {
            int r0  = bm + wm + mt * 16 + g;
            int col = coff + wn + nt * 8 + tg * 2;
            *(float2*)(Cout + (size_t)r0 * ldc + col) =
                make_float2(acc[mt][nt][0], acc[mt][nt][1]);
            *(float2*)(Cout + (size_t)(r0 + 8) * ldc + col) =
                make_float2(acc[mt][nt][2], acc[mt][nt][3]);
        }
    }
}

// ---------------- RoPE: rotate fp32 -> write fp16 (q scaled) ---------------
__global__ void rope_kernel(const float* __restrict__ q,
                            const float* __restrict__ k) {
    const int NH = H_ + KV_;
    int idx = blockIdx.x * blockDim.x + threadIdx.x;
    const int total = M_TOK * NH * (D_ / 2);
    if (idx >= total) return;

    int p   = idx & 31;
    int hh  = (idx >> 5) % NH;
    int tok = idx / (32 * NH);
    int tseq = tok & (T_ - 1);

    float inv = powf(10000.0f, -(float)p / 32.0f);
    float ang = (float)tseq * inv;
    float s, c;
    sincosf(ang, &s, &c);

    const float SCq = 0.125f * 1.4426950408889634f;

    const float* src;
    __half2* dst;
    float scale;
    if (hh < H_) {
        src = q + (size_t)tok * C_ + hh * D_ + 2 * p;
        dst = (__half2*)(g_qh + (size_t)tok * C_ + hh * D_) + p;
        scale = SCq;
    } else {
        src = k + (size_t)tok * KVDIM + (hh - H_) * D_ + 2 * p;
        dst = (__half2*)(g_kh + (size_t)tok * KVDIM + (hh - H_) * D_) + p;
        scale = 1.0f;
    }
    float e0 = src[0], e1 = src[1];
    *dst = __floats2half2_rn((e0 * c - e1 * s) * scale,
                             (e1 * c + e0 * s) * scale);
}

// ---------------- fp16 flash attention (FA2 fragment identity) -------------
// 128 threads / 4 warps, BQ=64 (16 rows/warp), BK=64, double-buffered K/V.
// K smem [t][d] fp16 pad 36 words; V smem [t/2][d][2] pad 68 words.
#define KW2 36
#define VW2 68
#define KSTG (64 * KW2)   // 2304 words
#define VSTG (32 * VW2)   // 2176 words
#define SMEM_F ((2 * KSTG + 2 * VSTG) * 4)   // 35840 B

__global__ void __launch_bounds__(128, 3)
flash_tc(const __half* __restrict__ Q, const __half* __restrict__ K,
         const __half* __restrict__ Vp, __half* __restrict__ O) {
    extern __shared__ uint32_t fsm[];
    const uint32_t sbase = smem_u32(fsm);

    const int tid  = threadIdx.x;
    const int warp = tid >> 5;
    const int lane = tid & 31;
    const int g    = lane >> 2;
    const int tg   = lane & 3;

    const int qi = blockIdx.x;
    const int bh = blockIdx.y;
    const int b  = bh >> 5;
    const int h  = bh & 31;
    const int hk = h >> 2;
    const int q0 = qi * 64;
    const int qrow = warp * 16;
    const int bT = b * T_;

#define ISSUE_KV(j, s)                                                      \
    do {                                                                    \
        uint32_t kb = sbase + (s) * (KSTG * 4);                             \
        uint32_t vb = sbase + (2 * KSTG + (s) * VSTG) * 4;                  \
        int k0i = (j) * 64;                                                 \
        _Pragma("unroll")                                                   \
        for (int l = 0; l < 4; ++l) {                                       \
            int id = l * 128 + tid;                                         \
            int r = id >> 3, c8 = id & 7;                                   \
            cpa16(kb + (uint32_t)(r * KW2 + c8 * 4) * 4,                    \
                  K + (size_t)(bT + k0i + r) * KVDIM + hk * D_ + c8 * 8);   \
        }                                                                   \
        _Pragma("unroll")                                                   \
        for (int l = 0; l < 4; ++l) {                                       \
            int id = l * 128 + tid;                                         \
            int t2 = id >> 4, c16 = id & 15;                                \
            cpa16(vb + (uint32_t)(t2 * VW2 + c16 * 4) * 4,                  \
                  Vp + ((size_t)((bT + k0i) >> 1) + t2) * (2 * KVDIM) +     \
                      hk * 128 + c16 * 8);                                  \
        }                                                                   \
    } while (0)

    // prologue: Q -> K-stage-1 area; KV tile 0 -> stage 0
    {
        uint32_t qb = sbase + KSTG * 4;
#pragma unroll
        for (int l = 0; l < 4; ++l) {
            int id = l * 128 + tid;
            int r = id >> 3, c8 = id & 7;
            cpa16(qb + (uint32_t)(r * KW2 + c8 * 4) * 4,
                  Q + (size_t)(bT + q0 + r) * C_ + h * D_ + c8 * 8);
        }
        cpa_commit();
    }
    ISSUE_KV(0, 0);
    cpa_commit();

    cpa_wait<1>();
    __syncthreads();

    uint32_t qf[4][4];
    {
        const uint32_t* Qs = fsm + KSTG;
#pragma unroll
        for (int c = 0; c < 4; ++c) {
            qf[c][0] = Qs[(qrow + g)     * KW2 + 8 * c + tg];
            qf[c][1] = Qs[(qrow + g + 8) * KW2 + 8 * c + tg];
            qf[c][2] = Qs[(qrow + g)     * KW2 + 8 * c + tg + 4];
            qf[c][3] = Qs[(qrow + g + 8) * KW2 + 8 * c + tg + 4];
        }
    }
    __syncthreads();

    if (qi >= 1) {
        ISSUE_KV(1, 1);
        cpa_commit();
    }

    float m1 = -INFINITY, m2 = -INFINITY, l1 = 0.0f, l2 = 0.0f;
    float oacc[8][4];
#pragma unroll
    for (int nt = 0; nt < 8; ++nt)
#pragma unroll
        for (int c = 0; c < 4; ++c) oacc[nt][c] = 0.0f;

    for (int j = 0; j <= qi; ++j) {
        if (j < qi) cpa_wait<1>(); else cpa_wait<0>();
        __syncthreads();

        const uint32_t* Ks = fsm + (j & 1) * KSTG;
        const uint32_t* Vs = fsm + 2 * KSTG + (j & 1) * VSTG;
        const int k0 = j * 64;

        // S = Q K^T (16x64 per warp), exp2 domain (scale folded into Q)
        float sacc[8][4];
#pragma unroll
        for (int nt = 0; nt < 8; ++nt)
#pragma unroll
            for (int c = 0; c < 4; ++c) sacc[nt][c] = 0.0f;

#pragma unroll
        for (int nt = 0; nt < 8; ++nt) {
#pragma unroll
            for (int c = 0; c < 4; ++c) {
                uint32_t bf[2];
                bf[0] = Ks[(nt * 8 + g) * KW2 + 8 * c + tg];
                bf[1] = Ks[(nt * 8 + g) * KW2 + 8 * c + tg + 4];
                mma_f16(sacc[nt], qf[c], bf);
            }
        }

        if (j == qi) {
            int r1 = q0 + qrow + g, r2 = r1 + 8;
#pragma unroll
            for (int nt = 0; nt < 8; ++nt) {
                int c0 = k0 + nt * 8 + tg * 2;
                if (c0     > r1) sacc[nt][0] = -INFINITY;
                if (c0 + 1 > r1) sacc[nt][1] = -INFINITY;
                if (c0     > r2) sacc[nt][2] = -INFINITY;
                if (c0 + 1 > r2) sacc[nt][3] = -INFINITY;
            }
        }

        float a1 = -INFINITY, a2 = -INFINITY;
#pragma unroll
        for (int nt = 0; nt < 8; ++nt) {
            a1 = fmaxf(a1, fmaxf(sacc[nt][0], sacc[nt][1]));
            a2 = fmaxf(a2, fmaxf(sacc[nt][2], sacc[nt][3]));
        }
        a1 = fmaxf(a1, __shfl_xor_sync(0xffffffff, a1, 1));
        a1 = fmaxf(a1, __shfl_xor_sync(0xffffffff, a1, 2));
        a2 = fmaxf(a2, __shfl_xor_sync(0xffffffff, a2, 1));
        a2 = fmaxf(a2, __shfl_xor_sync(0xffffffff, a2, 2));

        float mn1 = fmaxf(m1, a1), mn2 = fmaxf(m2, a2);
        float al1 = ex2f(m1 - mn1), al2 = ex2f(m2 - mn2);

        float s1 = 0.0f, s2 = 0.0f;
#pragma unroll
        for (int nt = 0; nt < 8; ++nt) {
            sacc[nt][0] = ex2f(sacc[nt][0] - mn1);
            sacc[nt][1] = ex2f(sacc[nt][1] - mn1);
            sacc[nt][2] = ex2f(sacc[nt][2] - mn2);
            sacc[nt][3] = ex2f(sacc[nt][3] - mn2);
            s1 += sacc[nt][0] + sacc[nt][1];
            s2 += sacc[nt][2] + sacc[nt][3];
        }
        s1 += __shfl_xor_sync(0xffffffff, s1, 1);
        s1 += __shfl_xor_sync(0xffffffff, s1, 2);
        s2 += __shfl_xor_sync(0xffffffff, s2, 1);
        s2 += __shfl_xor_sync(0xffffffff, s2, 2);

        l1 = l1 * al1 + s1;
        l2 = l2 * al2 + s2;
        m1 = mn1;
        m2 = mn2;

#pragma unroll
        for (int nt = 0; nt < 8; ++nt) {
            oacc[nt][0] *= al1; oacc[nt][1] *= al1;
            oacc[nt][2] *= al2; oacc[nt][3] *= al2;
        }

        // O += P V : C-frag of S IS the A-frag of PV (fp16 identity)
#pragma unroll
        for (int c = 0; c < 4; ++c) {
            uint32_t af[4];
            af[0] = packh2(sacc[2 * c][0],     sacc[2 * c][1]);
            af[1] = packh2(sacc[2 * c][2],     sacc[2 * c][3]);
            af[2] = packh2(sacc[2 * c + 1][0], sacc[2 * c + 1][1]);
            af[3] = packh2(sacc[2 * c + 1][2], sacc[2 * c + 1][3]);
#pragma unroll
            for (int nt = 0; nt < 8; ++nt) {
                uint32_t bf[2];
                bf[0] = Vs[(8 * c + tg)     * VW2 + nt * 8 + g];
                bf[1] = Vs[(8 * c + tg + 4) * VW2 + nt * 8 + g];
                mma_f16(oacc[nt], af, bf);
            }
        }

        __syncthreads();
        if (j + 2 <= qi) {
            ISSUE_KV(j + 2, j & 1);
            cpa_commit();
        }
    }

    // epilogue: normalize, write fp16 att [tok, H*D]
    float i1 = 1.0f / l1, i2 = 1.0f / l2;
    int r1 = q0 + qrow + g, r2 = r1 + 8;
#pragma unroll
    for (int nt = 0; nt < 8; ++nt) {
        int col = h * D_ + nt * 8 + tg * 2;
        __half2 lo = __floats2half2_rn(oacc[nt][0] * i1, oacc[nt][1] * i1);
        __half2 hi = __floats2half2_rn(oacc[nt][2] * i2, oacc[nt][3] * i2);
        *(__half2*)(O + (size_t)(bT + r1) * C_ + col) = lo;
        *(__half2*)(O + (size_t)(bT + r2) * C_ + col) = hi;
    }
}

// ---------------------------------------------------------------------------
extern "C" void kernel_launch(void* const* d_in, const int* in_sizes, int n_in,
                              void* d_out, int out_size) {
    const float* x  = (const float*)d_in[0];
    const float* Wq = (const float*)d_in[1];
    const float* Wk = (const float*)d_in[2];
    const float* Wv = (const float*)d_in[3];
    const float* Wp = (const float*)d_in[4];
    float* out = (float*)d_out;

    float *q, *k;
    __half *qh, *kh, *vp, *xh, *wqkvh, *wph, *atth;
    cudaGetSymbolAddress((void**)&q,     g_q);
    cudaGetSymbolAddress((void**)&k,     g_k);
    cudaGetSymbolAddress((void**)&qh,    g_qh);
    cudaGetSymbolAddress((void**)&kh,    g_kh);
    cudaGetSymbolAddress((void**)&vp,    g_vp);
    cudaGetSymbolAddress((void**)&xh,    g_xh);
    cudaGetSymbolAddress((void**)&wqkvh, g_wqkvh);
    cudaGetSymbolAddress((void**)&wph,   g_wph);
    cudaGetSymbolAddress((void**)&atth,  g_atth);

    cudaFuncSetAttribute(gemm_hp<1>,
                         cudaFuncAttributeMaxDynamicSharedMemorySize, SMEM_G);
    cudaFuncSetAttribute(gemm_hp<0>,
                         cudaFuncAttributeMaxDynamicSharedMemorySize, SMEM_G);
    cudaFuncSetAttribute(flash_tc,
                         cudaFuncAttributeMaxDynamicSharedMemorySize, SMEM_F);

    // 1. fp16 pre-conversion + weight interleave
    cvt_pack<<<(M_TOK * C_ / 4 + 255) / 256, 256>>>(x, Wq, Wk, Wv, Wp);

    // 2. fused QKV projection (fp16 mma; q/k fp32, v packed fp16)
    gemm_hp<1><<<dim3(NQKV / 128, M_TOK / 128), 256, SMEM_G>>>(
        xh, wqkvh, nullptr, M_TOK, NQKV, C_);

    // 3. RoPE: fp32 -> fp16 (q scaled by 1/sqrt(D)*log2e)
    int total_pairs = M_TOK * (H_ + KV_) * (D_ / 2);
    rope_kernel<<<(total_pairs + 255) / 256, 256>>>(q, k);

    // 4. causal flash attention with GQA (fp16 mma)
    flash_tc<<<dim3(T_ / 64, B_ * H_), 128, SMEM_F>>>(qh, kh, vp, atth);

    // 5. output projection (fp16 mma)
    gemm_hp<0><<<dim3(C_ / 128, M_TOK / 128), 256, SMEM_G>>>(
        atth, wph, out, M_TOK, C_, C_);
}

// round 10
// speedup vs baseline: 7.6753x; 1.1632x over previous
#include <cuda_runtime.h>
#include <cuda_fp16.h>
#include <math.h>
#include <stdint.h>

#define B_    4
#define T_    1024
#define C_    2048
#define H_    32
#define KV_   8
#define D_    64
#define M_TOK 4096
#define KVDIM 512
#define NQKV  3072          // 2048 q + 512 k + 512 v

// ---------------- scratch (device globals; no allocation allowed) ----------
__device__ __half g_qh[M_TOK * C_];         // fp16 q post-rope (scaled)
__device__ __half g_kh[M_TOK * KVDIM];      // fp16 k post-rope
__device__ __half g_vp[M_TOK * KVDIM];      // fp16 v, [tok/2][dk][2] packed
__device__ __half g_xh[M_TOK * C_];         // fp16(x)       [m][k]
__device__ __half g_wqkvh[C_ * NQKV];       // fp16 weights  [k/2][n][2]
__device__ __half g_wph[C_ * C_];           // fp16(Wp)      [k/2][n][2]
__device__ __half g_atth[M_TOK * C_];       // fp16 attention out
__device__ float2 g_rope[T_ * 32];          // cos/sin table [t][pair]

// ------------------------- helpers -----------------------------------------
__device__ __forceinline__ float ex2f(float x) {
    float r;
    asm("ex2.approx.f32 %0, %1;" : "=f"(r) : "f"(x));
    return r;
}
__device__ __forceinline__ uint32_t packh2(float a, float b) {
    __half2 h = __floats2half2_rn(a, b);
    return *(uint32_t*)&h;
}
__device__ __forceinline__ void mma_f16(float c[4], const uint32_t a[4],
                                        const uint32_t b[2]) {
    asm volatile(
        "mma.sync.aligned.m16n8k16.row.col.f32.f16.f16.f32 "
        "{%0,%1,%2,%3}, {%4,%5,%6,%7}, {%8,%9}, {%0,%1,%2,%3};"
        : "+f"(c[0]), "+f"(c[1]), "+f"(c[2]), "+f"(c[3])
        : "r"(a[0]), "r"(a[1]), "r"(a[2]), "r"(a[3]), "r"(b[0]), "r"(b[1]));
}
__device__ __forceinline__ uint32_t smem_u32(const void* p) {
    uint32_t a;
    asm("{ .reg .u64 t; cvta.to.shared.u64 t, %1; cvt.u32.u64 %0, t; }"
        : "=r"(a) : "l"(p));
    return a;
}
__device__ __forceinline__ void cpa16(uint32_t dst, const void* src) {
    asm volatile("cp.async.cg.shared.global [%0], [%1], 16;"
                 :: "r"(dst), "l"(src) : "memory");
}
__device__ __forceinline__ void cpa_commit() {
    asm volatile("cp.async.commit_group;" ::: "memory");
}
template <int N> __device__ __forceinline__ void cpa_wait() {
    asm volatile("cp.async.wait_group %0;" :: "n"(N) : "memory");
}

// ---------------- fp16 pre-conversion / weight interleave / rope table -----
__global__ void cvt_pack(const float* __restrict__ x,
                         const float* __restrict__ Wq,
                         const float* __restrict__ Wk,
                         const float* __restrict__ Wv,
                         const float* __restrict__ Wp) {
    int i4 = blockIdx.x * blockDim.x + threadIdx.x;

    if (i4 < T_ * 32) {
        int t = i4 >> 5, p = i4 & 31;
        float inv = powf(10000.0f, -(float)p / 32.0f);
        float s, c;
        sincosf((float)t * inv, &s, &c);
        g_rope[i4] = make_float2(c, s);
    }
    if (i4 < M_TOK * C_ / 4) {
        float4 v = ((const float4*)x)[i4];
        __half2* dst = (__half2*)(g_xh) + i4 * 2;
        dst[0] = __floats2half2_rn(v.x, v.y);
        dst[1] = __floats2half2_rn(v.z, v.w);
    }
    if (i4 < (C_ / 2) * (NQKV / 4)) {
        int r = i4 / (NQKV / 4);
        int n = (i4 % (NQKV / 4)) * 4;
        int k0 = 2 * r;
        const float *s0, *s1;
        if (n < 2048)      { s0 = Wq + (size_t)k0 * 2048 + n;
                             s1 = Wq + (size_t)(k0 + 1) * 2048 + n; }
        else if (n < 2560) { s0 = Wk + (size_t)k0 * 512 + (n - 2048);
                             s1 = Wk + (size_t)(k0 + 1) * 512 + (n - 2048); }
        else               { s0 = Wv + (size_t)k0 * 512 + (n - 2560);
                             s1 = Wv + (size_t)(k0 + 1) * 512 + (n - 2560); }
        float4 a = *(const float4*)s0;
        float4 b = *(const float4*)s1;
        __half2* dst = (__half2*)(g_wqkvh + (size_t)r * 2 * NQKV + n * 2);
        dst[0] = __floats2half2_rn(a.x, b.x);
        dst[1] = __floats2half2_rn(a.y, b.y);
        dst[2] = __floats2half2_rn(a.z, b.z);
        dst[3] = __floats2half2_rn(a.w, b.w);
    }
    if (i4 < (C_ / 2) * (C_ / 4)) {
        int r = i4 / (C_ / 4);
        int n = (i4 % (C_ / 4)) * 4;
        float4 a = *(const float4*)(Wp + (size_t)(2 * r) * C_ + n);
        float4 b = *(const float4*)(Wp + (size_t)(2 * r + 1) * C_ + n);
        __half2* dst = (__half2*)(g_wph + (size_t)r * 2 * C_ + n * 2);
        dst[0] = __floats2half2_rn(a.x, b.x);
        dst[1] = __floats2half2_rn(a.y, b.y);
        dst[2] = __floats2half2_rn(a.z, b.z);
        dst[3] = __floats2half2_rn(a.w, b.w);
    }
}

// ============ fp16 cp.async 3-stage GEMM, K-slab 64 ========================
// 128x128x64 slab, 8 warps (2x4), warp tile 64x32, m16n8k16, f32 accum.
// A smem [128][AW] words ([m][k] half2); B smem [32][BW] words ([kpair][n]).
#define AW 36     // 32 data + 4 pad
#define BW 136    // 128 data + 8 pad
#define A_WORDS (128 * AW)    // 4608
#define B_WORDS (32 * BW)     // 4352
#define STG_W (A_WORDS + B_WORDS)
#define SMEM_G (3 * STG_W * 4)   // 107520 B
#define CW 68     // V repack staging

template <int SPLIT>
__global__ void __launch_bounds__(256)
gemm_hp(const __half* __restrict__ A, const __half* __restrict__ Bm,
        float* __restrict__ C0, int M, int N, int K) {
    extern __shared__ uint32_t sm[];

    const int tid  = threadIdx.x;
    const int bm   = blockIdx.y * 128;
    const int bn   = blockIdx.x * 128;
    const int warp = tid >> 5;
    const int lane = tid & 31;
    const int g    = lane >> 2;
    const int tg   = lane & 3;
    const int wm   = (warp >> 2) * 64;
    const int wn   = (warp & 3) * 32;
    const int nslab = K >> 6;

    const uint32_t sbase = smem_u32(sm);

    float acc[4][4][4];
#pragma unroll
    for (int i = 0; i < 4; ++i)
#pragma unroll
        for (int j = 0; j < 4; ++j)
#pragma unroll
            for (int c = 0; c < 4; ++c) acc[i][j][c] = 0.0f;

#define ISSUE_STAGE(s, kb)                                                  \
    do {                                                                    \
        uint32_t ab = sbase + (s) * (STG_W * 4);                            \
        uint32_t bb = ab + A_WORDS * 4;                                     \
        _Pragma("unroll")                                                   \
        for (int l = 0; l < 4; ++l) {                                       \
            int id = l * 256 + tid;                                         \
            int row = id >> 3, wo = (id & 7) * 4;                           \
            cpa16(ab + (uint32_t)(row * AW + wo) * 4,                       \
                  A + (size_t)(bm + row) * K + (kb) + wo * 2);              \
        }                                                                   \
        _Pragma("unroll")                                                   \
        for (int l = 0; l < 4; ++l) {                                       \
            int id = l * 256 + tid;                                         \
            int r = id >> 5, nw = (id & 31) * 4;                            \
            cpa16(bb + (uint32_t)(r * BW + nw) * 4,                         \
                  Bm + ((size_t)((kb) >> 1) + r) * (2 * N) +                \
                      (size_t)(bn + nw) * 2);                               \
        }                                                                   \
    } while (0)

    ISSUE_STAGE(0, 0);
    cpa_commit();
    ISSUE_STAGE(1, 64);
    cpa_commit();

    for (int i = 0; i < nslab; ++i) {
        if (i + 1 < nslab) cpa_wait<1>(); else cpa_wait<0>();
        __syncthreads();
        if (i + 2 < nslab) {
            ISSUE_STAGE((i + 2) % 3, (i + 2) << 6);
            cpa_commit();
        }

        const uint32_t* a_s = sm + (i % 3) * STG_W;
        const uint32_t* b_s = a_s + A_WORDS;

#pragma unroll
        for (int ks = 0; ks < 4; ++ks) {        // four k16 chunks
            const int kp = ks * 8;
            uint32_t af[4][4], bf[4][2];
#pragma unroll
            for (int mt = 0; mt < 4; ++mt) {
                int m0 = wm + mt * 16;
                af[mt][0] = a_s[(m0 + g)     * AW + kp + tg];
                af[mt][1] = a_s[(m0 + g + 8) * AW + kp + tg];
                af[mt][2] = a_s[(m0 + g)     * AW + kp + tg + 4];
                af[mt][3] = a_s[(m0 + g + 8) * AW + kp + tg + 4];
            }
#pragma unroll
            for (int nt = 0; nt < 4; ++nt) {
                int n0 = wn + nt * 8;
                bf[nt][0] = b_s[(kp + tg)     * BW + n0 + g];
                bf[nt][1] = b_s[(kp + tg + 4) * BW + n0 + g];
            }
#pragma unroll
            for (int mt = 0; mt < 4; ++mt)
#pragma unroll
                for (int nt = 0; nt < 4; ++nt)
                    mma_f16(acc[mt][nt], af[mt], bf[nt]);
        }
        __syncthreads();
    }

    if (SPLIT && bn >= 2560) {
        // ---- V tile: repack through smem into [tok/2][dk][2] fp16 ----
#pragma unroll
        for (int mt = 0; mt < 4; ++mt)
#pragma unroll
            for (int nt = 0; nt < 4; ++nt) {
                int r0 = wm + mt * 16 + g;
                int cw = (wn + nt * 8 + tg * 2) >> 1;
                sm[r0 * CW + cw]       = packh2(acc[mt][nt][0], acc[mt][nt][1]);
                sm[(r0 + 8) * CW + cw] = packh2(acc[mt][nt][2], acc[mt][nt][3]);
            }
        __syncthreads();
        uint32_t* vp32 = (uint32_t*)g_vp;
#pragma unroll
        for (int it = 0; it < 16; ++it) {
            int id = it * 256 + tid;
            int tp = id >> 6, cw = id & 63;
            uint32_t a = sm[(2 * tp) * CW + cw];
            uint32_t b = sm[(2 * tp + 1) * CW + cw];
            __half2 ah = *(__half2*)&a, bh = *(__half2*)&b;
            uint2 o;
            o.x = packh2(__low2float(ah),  __low2float(bh));
            o.y = packh2(__high2float(ah), __high2float(bh));
            *(uint2*)(vp32 + ((size_t)(bm >> 1) + tp) * 512 +
                      (bn - 2560) + 2 * cw) = o;
        }
        return;
    }

    if (SPLIT) {
        // ---- q/k tile: fused RoPE, write fp16 (q scaled for softmax) ----
        const float SCq = 0.125f * 1.4426950408889634f;
        const bool isq = (bn < 2048);
        const float scale = isq ? SCq : 1.0f;
        __half* dst = isq ? g_qh : g_kh;
        const int ldc = isq ? 2048 : 512;
        const int coff = isq ? bn : bn - 2048;
#pragma unroll
        for (int mt = 0; mt < 4; ++mt) {
#pragma unroll
            for (int nt = 0; nt < 4; ++nt) {
                int col = coff + wn + nt * 8 + tg * 2;
                int p = (col & 63) >> 1;
                int r0 = bm + wm + mt * 16 + g;
                float2 cs0 = g_rope[(r0 & (T_ - 1)) * 32 + p];
                float2 cs1 = g_rope[((r0 + 8) & (T_ - 1)) * 32 + p];
                float a0 = acc[mt][nt][0], a1 = acc[mt][nt][1];
                float a2 = acc[mt][nt][2], a3 = acc[mt][nt][3];
                *(__half2*)(dst + (size_t)r0 * ldc + col) =
                    __floats2half2_rn((a0 * cs0.x - a1 * cs0.y) * scale,
                                      (a1 * cs0.x + a0 * cs0.y) * scale);
                *(__half2*)(dst + (size_t)(r0 + 8) * ldc + col) =
                    __floats2half2_rn((a2 * cs1.x - a3 * cs1.y) * scale,
                                      (a3 * cs1.x + a2 * cs1.y) * scale);
            }
        }
        return;
    }

    // ---- plain fp32 output (out-proj) ----
#pragma unroll
    for (int mt = 0; mt < 4; ++mt) {
#pragma unroll
        for (int nt = 0; nt < 4; ++nt) {
            int r0  = bm + wm + mt * 16 + g;
            int col = bn + wn + nt * 8 + tg * 2;
            *(float2*)(C0 + (size_t)r0 * N + col) =
                make_float2(acc[mt][nt][0], acc[mt][nt][1]);
            *(float2*)(C0 + (size_t)(r0 + 8) * N + col) =
                make_float2(acc[mt][nt][2], acc[mt][nt][3]);
        }
    }
}

// ---------------- fp16 flash attention (FA2 fragment identity) -------------
#define KW2 36
#define VW2 68
#define KSTG (64 * KW2)
#define VSTG (32 * VW2)
#define SMEM_F ((2 * KSTG + 2 * VSTG) * 4)

__global__ void __launch_bounds__(128, 3)
flash_tc(const __half* __restrict__ Q, const __half* __restrict__ K,
         const __half* __restrict__ Vp, __half* __restrict__ O) {
    extern __shared__ uint32_t fsm[];
    const uint32_t sbase = smem_u32(fsm);

    const int tid  = threadIdx.x;
    const int warp = tid >> 5;
    const int lane = tid & 31;
    const int g    = lane >> 2;
    const int tg   = lane & 3;

    const int qi = blockIdx.x;
    const int bh = blockIdx.y;
    const int b  = bh >> 5;
    const int h  = bh & 31;
    const int hk = h >> 2;
    const int q0 = qi * 64;
    const int qrow = warp * 16;
    const int bT = b * T_;

#define ISSUE_KV(j, s)                                                      \
    do {                                                                    \
        uint32_t kb = sbase + (s) * (KSTG * 4);                             \
        uint32_t vb = sbase + (2 * KSTG + (s) * VSTG) * 4;                  \
        int k0i = (j) * 64;                                                 \
        _Pragma("unroll")                                                   \
        for (int l = 0; l < 4; ++l) {                                       \
            int id = l * 128 + tid;                                         \
            int r = id >> 3, c8 = id & 7;                                   \
            cpa16(kb + (uint32_t)(r * KW2 + c8 * 4) * 4,                    \
                  K + (size_t)(bT + k0i + r) * KVDIM + hk * D_ + c8 * 8);   \
        }                                                                   \
        _Pragma("unroll")                                                   \
        for (int l = 0; l < 4; ++l) {                                       \
            int id = l * 128 + tid;                                         \
            int t2 = id >> 4, c16 = id & 15;                                \
            cpa16(vb + (uint32_t)(t2 * VW2 + c16 * 4) * 4,                  \
                  Vp + ((size_t)((bT + k0i) >> 1) + t2) * (2 * KVDIM) +     \
                      hk * 128 + c16 * 8);                                  \
        }                                                                   \
    } while (0)

    {
        uint32_t qb = sbase + KSTG * 4;
#pragma unroll
        for (int l = 0; l < 4; ++l) {
            int id = l * 128 + tid;
            int r = id >> 3, c8 = id & 7;
            cpa16(qb + (uint32_t)(r * KW2 + c8 * 4) * 4,
                  Q + (size_t)(bT + q0 + r) * C_ + h * D_ + c8 * 8);
        }
        cpa_commit();
    }
    ISSUE_KV(0, 0);
    cpa_commit();

    cpa_wait<1>();
    __syncthreads();

    uint32_t qf[4][4];
    {
        const uint32_t* Qs = fsm + KSTG;
#pragma unroll
        for (int c = 0; c < 4; ++c) {
            qf[c][0] = Qs[(qrow + g)     * KW2 + 8 * c + tg];
            qf[c][1] = Qs[(qrow + g + 8) * KW2 + 8 * c + tg];
            qf[c][2] = Qs[(qrow + g)     * KW2 + 8 * c + tg + 4];
            qf[c][3] = Qs[(qrow + g + 8) * KW2 + 8 * c + tg + 4];
        }
    }
    __syncthreads();

    if (qi >= 1) {
        ISSUE_KV(1, 1);
        cpa_commit();
    }

    float m1 = -INFINITY, m2 = -INFINITY, l1 = 0.0f, l2 = 0.0f;
    float oacc[8][4];
#pragma unroll
    for (int nt = 0; nt < 8; ++nt)
#pragma unroll
        for (int c = 0; c < 4; ++c) oacc[nt][c] = 0.0f;

    for (int j = 0; j <= qi; ++j) {
        if (j < qi) cpa_wait<1>(); else cpa_wait<0>();
        __syncthreads();

        const uint32_t* Ks = fsm + (j & 1) * KSTG;
        const uint32_t* Vs = fsm + 2 * KSTG + (j & 1) * VSTG;
        const int k0 = j * 64;

        float sacc[8][4];
#pragma unroll
        for (int nt = 0; nt < 8; ++nt)
#pragma unroll
            for (int c = 0; c < 4; ++c) sacc[nt][c] = 0.0f;

#pragma unroll
        for (int nt = 0; nt < 8; ++nt) {
#pragma unroll
            for (int c = 0; c < 4; ++c) {
                uint32_t bf[2];
                bf[0] = Ks[(nt * 8 + g) * KW2 + 8 * c + tg];
                bf[1] = Ks[(nt * 8 + g) * KW2 + 8 * c + tg + 4];
                mma_f16(sacc[nt], qf[c], bf);
            }
        }

        if (j == qi) {
            int r1 = q0 + qrow + g, r2 = r1 + 8;
#pragma unroll
            for (int nt = 0; nt < 8; ++nt) {
                int c0 = k0 + nt * 8 + tg * 2;
                if (c0     > r1) sacc[nt][0] = -INFINITY;
                if (c0 + 1 > r1) sacc[nt][1] = -INFINITY;
                if (c0     > r2) sacc[nt][2] = -INFINITY;
                if (c0 + 1 > r2) sacc[nt][3] = -INFINITY;
            }
        }

        float a1 = -INFINITY, a2 = -INFINITY;
#pragma unroll
        for (int nt = 0; nt < 8; ++nt) {
            a1 = fmaxf(a1, fmaxf(sacc[nt][0], sacc[nt][1]));
            a2 = fmaxf(a2, fmaxf(sacc[nt][2], sacc[nt][3]));
        }
        a1 = fmaxf(a1, __shfl_xor_sync(0xffffffff, a1, 1));
        a1 = fmaxf(a1, __shfl_xor_sync(0xffffffff, a1, 2));
        a2 = fmaxf(a2, __shfl_xor_sync(0xffffffff, a2, 1));
        a2 = fmaxf(a2, __shfl_xor_sync(0xffffffff, a2, 2));

        float mn1 = fmaxf(m1, a1), mn2 = fmaxf(m2, a2);
        float al1 = ex2f(m1 - mn1), al2 = ex2f(m2 - mn2);

        float s1 = 0.0f, s2 = 0.0f;
#pragma unroll
        for (int nt = 0; nt < 8; ++nt) {
            sacc[nt][0] = ex2f(sacc[nt][0] - mn1);
            sacc[nt][1] = ex2f(sacc[nt][1] - mn1);
            sacc[nt][2] = ex2f(sacc[nt][2] - mn2);
            sacc[nt][3] = ex2f(sacc[nt][3] - mn2);
            s1 += sacc[nt][0] + sacc[nt][1];
            s2 += sacc[nt][2] + sacc[nt][3];
        }
        s1 += __shfl_xor_sync(0xffffffff, s1, 1);
        s1 += __shfl_xor_sync(0xffffffff, s1, 2);
        s2 += __shfl_xor_sync(0xffffffff, s2, 1);
        s2 += __shfl_xor_sync(0xffffffff, s2, 2);

        l1 = l1 * al1 + s1;
        l2 = l2 * al2 + s2;
        m1 = mn1;
        m2 = mn2;

#pragma unroll
        for (int nt = 0; nt < 8; ++nt) {
            oacc[nt][0] *= al1; oacc[nt][1] *= al1;
            oacc[nt][2] *= al2; oacc[nt][3] *= al2;
        }

#pragma unroll
        for (int c = 0; c < 4; ++c) {
            uint32_t af[4];
            af[0] = packh2(sacc[2 * c][0],     sacc[2 * c][1]);
            af[1] = packh2(sacc[2 * c][2],     sacc[2 * c][3]);
            af[2] = packh2(sacc[2 * c + 1][0], sacc[2 * c + 1][1]);
            af[3] = packh2(sacc[2 * c + 1][2], sacc[2 * c + 1][3]);
#pragma unroll
            for (int nt = 0; nt < 8; ++nt) {
                uint32_t bf[2];
                bf[0] = Vs[(8 * c + tg)     * VW2 + nt * 8 + g];
                bf[1] = Vs[(8 * c + tg + 4) * VW2 + nt * 8 + g];
                mma_f16(oacc[nt], af, bf);
            }
        }

        __syncthreads();
        if (j + 2 <= qi) {
            ISSUE_KV(j + 2, j & 1);
            cpa_commit();
        }
    }

    float i1 = 1.0f / l1, i2 = 1.0f / l2;
    int r1 = q0 + qrow + g, r2 = r1 + 8;
#pragma unroll
    for (int nt = 0; nt < 8; ++nt) {
        int col = h * D_ + nt * 8 + tg * 2;
        __half2 lo = __floats2half2_rn(oacc[nt][0] * i1, oacc[nt][1] * i1);
        __half2 hi = __floats2half2_rn(oacc[nt][2] * i2, oacc[nt][3] * i2);
        *(__half2*)(O + (size_t)(bT + r1) * C_ + col) = lo;
        *(__half2*)(O + (size_t)(bT + r2) * C_ + col) = hi;
    }
}

// ---------------------------------------------------------------------------
extern "C" void kernel_launch(void* const* d_in, const int* in_sizes, int n_in,
                              void* d_out, int out_size) {
    const float* x  = (const float*)d_in[0];
    const float* Wq = (const float*)d_in[1];
    const float* Wk = (const float*)d_in[2];
    const float* Wv = (const float*)d_in[3];
    const float* Wp = (const float*)d_in[4];
    float* out = (float*)d_out;

    __half *qh, *kh, *vp, *xh, *wqkvh, *wph, *atth;
    cudaGetSymbolAddress((void**)&qh,    g_qh);
    cudaGetSymbolAddress((void**)&kh,    g_kh);
    cudaGetSymbolAddress((void**)&vp,    g_vp);
    cudaGetSymbolAddress((void**)&xh,    g_xh);
    cudaGetSymbolAddress((void**)&wqkvh, g_wqkvh);
    cudaGetSymbolAddress((void**)&wph,   g_wph);
    cudaGetSymbolAddress((void**)&atth,  g_atth);

    cudaFuncSetAttribute(gemm_hp<1>,
                         cudaFuncAttributeMaxDynamicSharedMemorySize, SMEM_G);
    cudaFuncSetAttribute(gemm_hp<0>,
                         cudaFuncAttributeMaxDynamicSharedMemorySize, SMEM_G);
    cudaFuncSetAttribute(flash_tc,
                         cudaFuncAttributeMaxDynamicSharedMemorySize, SMEM_F);

    // 1. fp16 pre-conversion + weight interleave + rope table
    cvt_pack<<<(M_TOK * C_ / 4 + 255) / 256, 256>>>(x, Wq, Wk, Wv, Wp);

    // 2. fused QKV projection + RoPE epilogue (q/k fp16 rotated, v packed)
    gemm_hp<1><<<dim3(NQKV / 128, M_TOK / 128), 256, SMEM_G>>>(
        xh, wqkvh, nullptr, M_TOK, NQKV, C_);

    // 3. causal flash attention with GQA (fp16 mma)
    flash_tc<<<dim3(T_ / 64, B_ * H_), 128, SMEM_F>>>(qh, kh, vp, atth);

    // 4. output projection (fp16 mma)
    gemm_hp<0><<<dim3(C_ / 128, M_TOK / 128), 256, SMEM_G>>>(
        atth, wph, out, M_TOK, C_, C_);
}

// round 11
// speedup vs baseline: 8.1174x; 1.0576x over previous
#include <cuda_runtime.h>
#include <cuda_fp16.h>
#include <math.h>
#include <stdint.h>

#define B_    4
#define T_    1024
#define C_    2048
#define H_    32
#define KV_   8
#define D_    64
#define M_TOK 4096
#define KVDIM 512
#define NQKV  3072          // 2048 q + 512 k + 512 v

// ---------------- scratch (device globals; no allocation allowed) ----------
__device__ __half g_qh[M_TOK * C_];         // fp16 q post-rope (scaled)
__device__ __half g_kh[M_TOK * KVDIM];      // fp16 k post-rope
__device__ __half g_vp[M_TOK * KVDIM];      // fp16 v, [tok/2][dk][2] packed
__device__ __half g_xh[M_TOK * C_];         // fp16(x)       [m][k]
__device__ __half g_wqkvh[C_ * NQKV];       // fp16 weights  [k/2][n][2]
__device__ __half g_wph[C_ * C_];           // fp16(Wp)      [k/2][n][2]
__device__ __half g_atth[M_TOK * C_];       // fp16 attention out
__device__ float2 g_rope[T_ * 32];          // cos/sin table [t][pair]

// ------------------------- helpers -----------------------------------------
__device__ __forceinline__ float ex2f(float x) {
    float r;
    asm("ex2.approx.f32 %0, %1;" : "=f"(r) : "f"(x));
    return r;
}
__device__ __forceinline__ uint32_t packh2(float a, float b) {
    __half2 h = __floats2half2_rn(a, b);
    return *(uint32_t*)&h;
}
__device__ __forceinline__ void mma_f16(float c[4], const uint32_t a[4],
                                        const uint32_t b[2]) {
    asm volatile(
        "mma.sync.aligned.m16n8k16.row.col.f32.f16.f16.f32 "
        "{%0,%1,%2,%3}, {%4,%5,%6,%7}, {%8,%9}, {%0,%1,%2,%3};"
        : "+f"(c[0]), "+f"(c[1]), "+f"(c[2]), "+f"(c[3])
        : "r"(a[0]), "r"(a[1]), "r"(a[2]), "r"(a[3]), "r"(b[0]), "r"(b[1]));
}
__device__ __forceinline__ void ldsm4(uint32_t& r0, uint32_t& r1,
                                      uint32_t& r2, uint32_t& r3,
                                      uint32_t addr) {
    asm volatile(
        "ldmatrix.sync.aligned.m8n8.x4.shared.b16 {%0,%1,%2,%3}, [%4];"
        : "=r"(r0), "=r"(r1), "=r"(r2), "=r"(r3) : "r"(addr));
}
__device__ __forceinline__ uint32_t smem_u32(const void* p) {
    uint32_t a;
    asm("{ .reg .u64 t; cvta.to.shared.u64 t, %1; cvt.u32.u64 %0, t; }"
        : "=r"(a) : "l"(p));
    return a;
}
__device__ __forceinline__ void cpa16(uint32_t dst, const void* src) {
    asm volatile("cp.async.cg.shared.global [%0], [%1], 16;"
                 :: "r"(dst), "l"(src) : "memory");
}
__device__ __forceinline__ void cpa_commit() {
    asm volatile("cp.async.commit_group;" ::: "memory");
}
template <int N> __device__ __forceinline__ void cpa_wait() {
    asm volatile("cp.async.wait_group %0;" :: "n"(N) : "memory");
}

// ---------------- fp16 pre-conversion / weight interleave / rope table -----
__global__ void cvt_pack(const float* __restrict__ x,
                         const float* __restrict__ Wq,
                         const float* __restrict__ Wk,
                         const float* __restrict__ Wv,
                         const float* __restrict__ Wp) {
    int i4 = blockIdx.x * blockDim.x + threadIdx.x;

    if (i4 < T_ * 32) {
        int t = i4 >> 5, p = i4 & 31;
        float inv = powf(10000.0f, -(float)p / 32.0f);
        float s, c;
        sincosf((float)t * inv, &s, &c);
        g_rope[i4] = make_float2(c, s);
    }
    if (i4 < M_TOK * C_ / 4) {
        float4 v = ((const float4*)x)[i4];
        __half2* dst = (__half2*)(g_xh) + i4 * 2;
        dst[0] = __floats2half2_rn(v.x, v.y);
        dst[1] = __floats2half2_rn(v.z, v.w);
    }
    if (i4 < (C_ / 2) * (NQKV / 4)) {
        int r = i4 / (NQKV / 4);
        int n = (i4 % (NQKV / 4)) * 4;
        int k0 = 2 * r;
        const float *s0, *s1;
        if (n < 2048)      { s0 = Wq + (size_t)k0 * 2048 + n;
                             s1 = Wq + (size_t)(k0 + 1) * 2048 + n; }
        else if (n < 2560) { s0 = Wk + (size_t)k0 * 512 + (n - 2048);
                             s1 = Wk + (size_t)(k0 + 1) * 512 + (n - 2048); }
        else               { s0 = Wv + (size_t)k0 * 512 + (n - 2560);
                             s1 = Wv + (size_t)(k0 + 1) * 512 + (n - 2560); }
        float4 a = *(const float4*)s0;
        float4 b = *(const float4*)s1;
        __half2* dst = (__half2*)(g_wqkvh + (size_t)r * 2 * NQKV + n * 2);
        dst[0] = __floats2half2_rn(a.x, b.x);
        dst[1] = __floats2half2_rn(a.y, b.y);
        dst[2] = __floats2half2_rn(a.z, b.z);
        dst[3] = __floats2half2_rn(a.w, b.w);
    }
    if (i4 < (C_ / 2) * (C_ / 4)) {
        int r = i4 / (C_ / 4);
        int n = (i4 % (C_ / 4)) * 4;
        float4 a = *(const float4*)(Wp + (size_t)(2 * r) * C_ + n);
        float4 b = *(const float4*)(Wp + (size_t)(2 * r + 1) * C_ + n);
        __half2* dst = (__half2*)(g_wph + (size_t)r * 2 * C_ + n * 2);
        dst[0] = __floats2half2_rn(a.x, b.x);
        dst[1] = __floats2half2_rn(a.y, b.y);
        dst[2] = __floats2half2_rn(a.z, b.z);
        dst[3] = __floats2half2_rn(a.w, b.w);
    }
}

// ============ fp16 cp.async 2-stage GEMM, K-slab 64, 2 CTAs/SM =============
// 128x128x64 slab, 8 warps (2x4), warp tile 64x32, m16n8k16, f32 accum.
// A fragments via ldmatrix.x4; B scalar LDS (conflict-free).
#define AW 36     // 32 data + 4 pad (half2 words per A row)
#define BW 136    // 128 data + 8 pad
#define A_WORDS (128 * AW)    // 4608
#define B_WORDS (32 * BW)     // 4352
#define STG_W (A_WORDS + B_WORDS)
#define SMEM_G (2 * STG_W * 4)   // 71680 B -> 2 CTAs/SM
#define CW 68     // V repack staging

template <int SPLIT>
__global__ void __launch_bounds__(256, 2)
gemm_hp(const __half* __restrict__ A, const __half* __restrict__ Bm,
        float* __restrict__ C0, int M, int N, int K) {
    extern __shared__ uint32_t sm[];

    const int tid  = threadIdx.x;
    const int bm   = blockIdx.y * 128;
    const int bn   = blockIdx.x * 128;
    const int warp = tid >> 5;
    const int lane = tid & 31;
    const int g    = lane >> 2;
    const int tg   = lane & 3;
    const int wm   = (warp >> 2) * 64;
    const int wn   = (warp & 3) * 32;
    const int nslab = K >> 6;

    const uint32_t sbase = smem_u32(sm);
    // per-lane ldmatrix base (words): row wm+(lane&15), col-half (lane>>4)*4
    const uint32_t lds_a = ((wm + (lane & 15)) * AW + ((lane >> 4) << 2)) * 4;

    float acc[4][4][4];
#pragma unroll
    for (int i = 0; i < 4; ++i)
#pragma unroll
        for (int j = 0; j < 4; ++j)
#pragma unroll
            for (int c = 0; c < 4; ++c) acc[i][j][c] = 0.0f;

#define ISSUE_STAGE(s, kb)                                                  \
    do {                                                                    \
        uint32_t ab = sbase + (s) * (STG_W * 4);                            \
        uint32_t bb = ab + A_WORDS * 4;                                     \
        _Pragma("unroll")                                                   \
        for (int l = 0; l < 4; ++l) {                                       \
            int id = l * 256 + tid;                                         \
            int row = id >> 3, wo = (id & 7) * 4;                           \
            cpa16(ab + (uint32_t)(row * AW + wo) * 4,                       \
                  A + (size_t)(bm + row) * K + (kb) + wo * 2);              \
        }                                                                   \
        _Pragma("unroll")                                                   \
        for (int l = 0; l < 4; ++l) {                                       \
            int id = l * 256 + tid;                                         \
            int r = id >> 5, nw = (id & 31) * 4;                            \
            cpa16(bb + (uint32_t)(r * BW + nw) * 4,                         \
                  Bm + ((size_t)((kb) >> 1) + r) * (2 * N) +                \
                      (size_t)(bn + nw) * 2);                               \
        }                                                                   \
    } while (0)

    ISSUE_STAGE(0, 0);
    cpa_commit();

    for (int i = 0; i < nslab; ++i) {
        if (i + 1 < nslab) {
            ISSUE_STAGE((i + 1) & 1, (i + 1) << 6);
            cpa_commit();
            cpa_wait<1>();
        } else {
            cpa_wait<0>();
        }
        __syncthreads();

        const uint32_t a_sm = sbase + (i & 1) * (STG_W * 4) + lds_a;
        const uint32_t* b_s = sm + (i & 1) * STG_W + A_WORDS;

#pragma unroll
        for (int ks = 0; ks < 4; ++ks) {        // four k16 chunks
            const int kp = ks * 8;
            uint32_t af[4][4], bf[4][2];
#pragma unroll
            for (int mt = 0; mt < 4; ++mt)
                ldsm4(af[mt][0], af[mt][1], af[mt][2], af[mt][3],
                      a_sm + (uint32_t)(mt * 16 * AW + kp) * 4);
#pragma unroll
            for (int nt = 0; nt < 4; ++nt) {
                int n0 = wn + nt * 8;
                bf[nt][0] = b_s[(kp + tg)     * BW + n0 + g];
                bf[nt][1] = b_s[(kp + tg + 4) * BW + n0 + g];
            }
#pragma unroll
            for (int mt = 0; mt < 4; ++mt)
#pragma unroll
                for (int nt = 0; nt < 4; ++nt)
                    mma_f16(acc[mt][nt], af[mt], bf[nt]);
        }
        __syncthreads();
    }

    if (SPLIT && bn >= 2560) {
        // ---- V tile: repack through smem into [tok/2][dk][2] fp16 ----
#pragma unroll
        for (int mt = 0; mt < 4; ++mt)
#pragma unroll
            for (int nt = 0; nt < 4; ++nt) {
                int r0 = wm + mt * 16 + g;
                int cw = (wn + nt * 8 + tg * 2) >> 1;
                sm[r0 * CW + cw]       = packh2(acc[mt][nt][0], acc[mt][nt][1]);
                sm[(r0 + 8) * CW + cw] = packh2(acc[mt][nt][2], acc[mt][nt][3]);
            }
        __syncthreads();
        uint32_t* vp32 = (uint32_t*)g_vp;
#pragma unroll
        for (int it = 0; it < 16; ++it) {
            int id = it * 256 + tid;
            int tp = id >> 6, cw = id & 63;
            uint32_t a = sm[(2 * tp) * CW + cw];
            uint32_t b = sm[(2 * tp + 1) * CW + cw];
            __half2 ah = *(__half2*)&a, bh = *(__half2*)&b;
            uint2 o;
            o.x = packh2(__low2float(ah),  __low2float(bh));
            o.y = packh2(__high2float(ah), __high2float(bh));
            *(uint2*)(vp32 + ((size_t)(bm >> 1) + tp) * 512 +
                      (bn - 2560) + 2 * cw) = o;
        }
        return;
    }

    if (SPLIT) {
        // ---- q/k tile: fused RoPE, write fp16 (q scaled for softmax) ----
        const float SCq = 0.125f * 1.4426950408889634f;
        const bool isq = (bn < 2048);
        const float scale = isq ? SCq : 1.0f;
        __half* dst = isq ? g_qh : g_kh;
        const int ldc = isq ? 2048 : 512;
        const int coff = isq ? bn : bn - 2048;
#pragma unroll
        for (int mt = 0; mt < 4; ++mt) {
#pragma unroll
            for (int nt = 0; nt < 4; ++nt) {
                int col = coff + wn + nt * 8 + tg * 2;
                int p = (col & 63) >> 1;
                int r0 = bm + wm + mt * 16 + g;
                float2 cs0 = g_rope[(r0 & (T_ - 1)) * 32 + p];
                float2 cs1 = g_rope[((r0 + 8) & (T_ - 1)) * 32 + p];
                float a0 = acc[mt][nt][0], a1 = acc[mt][nt][1];
                float a2 = acc[mt][nt][2], a3 = acc[mt][nt][3];
                *(__half2*)(dst + (size_t)r0 * ldc + col) =
                    __floats2half2_rn((a0 * cs0.x - a1 * cs0.y) * scale,
                                      (a1 * cs0.x + a0 * cs0.y) * scale);
                *(__half2*)(dst + (size_t)(r0 + 8) * ldc + col) =
                    __floats2half2_rn((a2 * cs1.x - a3 * cs1.y) * scale,
                                      (a3 * cs1.x + a2 * cs1.y) * scale);
            }
        }
        return;
    }

    // ---- plain fp32 output (out-proj) ----
#pragma unroll
    for (int mt = 0; mt < 4; ++mt) {
#pragma unroll
        for (int nt = 0; nt < 4; ++nt) {
            int r0  = bm + wm + mt * 16 + g;
            int col = bn + wn + nt * 8 + tg * 2;
            *(float2*)(C0 + (size_t)r0 * N + col) =
                make_float2(acc[mt][nt][0], acc[mt][nt][1]);
            *(float2*)(C0 + (size_t)(r0 + 8) * N + col) =
                make_float2(acc[mt][nt][2], acc[mt][nt][3]);
        }
    }
}

// ---------------- fp16 flash attention (FA2 fragment identity) -------------
#define KW2 36
#define VW2 68
#define KSTG (64 * KW2)
#define VSTG (32 * VW2)
#define SMEM_F ((2 * KSTG + 2 * VSTG) * 4)

__global__ void __launch_bounds__(128, 3)
flash_tc(const __half* __restrict__ Q, const __half* __restrict__ K,
         const __half* __restrict__ Vp, __half* __restrict__ O) {
    extern __shared__ uint32_t fsm[];
    const uint32_t sbase = smem_u32(fsm);

    const int tid  = threadIdx.x;
    const int warp = tid >> 5;
    const int lane = tid & 31;
    const int g    = lane >> 2;
    const int tg   = lane & 3;

    const int qi = blockIdx.x;
    const int bh = blockIdx.y;
    const int b  = bh >> 5;
    const int h  = bh & 31;
    const int hk = h >> 2;
    const int q0 = qi * 64;
    const int qrow = warp * 16;
    const int bT = b * T_;

#define ISSUE_KV(j, s)                                                      \
    do {                                                                    \
        uint32_t kb = sbase + (s) * (KSTG * 4);                             \
        uint32_t vb = sbase + (2 * KSTG + (s) * VSTG) * 4;                  \
        int k0i = (j) * 64;                                                 \
        _Pragma("unroll")                                                   \
        for (int l = 0; l < 4; ++l) {                                       \
            int id = l * 128 + tid;                                         \
            int r = id >> 3, c8 = id & 7;                                   \
            cpa16(kb + (uint32_t)(r * KW2 + c8 * 4) * 4,                    \
                  K + (size_t)(bT + k0i + r) * KVDIM + hk * D_ + c8 * 8);   \
        }                                                                   \
        _Pragma("unroll")                                                   \
        for (int l = 0; l < 4; ++l) {                                       \
            int id = l * 128 + tid;                                         \
            int t2 = id >> 4, c16 = id & 15;                                \
            cpa16(vb + (uint32_t)(t2 * VW2 + c16 * 4) * 4,                  \
                  Vp + ((size_t)((bT + k0i) >> 1) + t2) * (2 * KVDIM) +     \
                      hk * 128 + c16 * 8);                                  \
        }                                                                   \
    } while (0)

    {
        uint32_t qb = sbase + KSTG * 4;
#pragma unroll
        for (int l = 0; l < 4; ++l) {
            int id = l * 128 + tid;
            int r = id >> 3, c8 = id & 7;
            cpa16(qb + (uint32_t)(r * KW2 + c8 * 4) * 4,
                  Q + (size_t)(bT + q0 + r) * C_ + h * D_ + c8 * 8);
        }
        cpa_commit();
    }
    ISSUE_KV(0, 0);
    cpa_commit();

    cpa_wait<1>();
    __syncthreads();

    uint32_t qf[4][4];
    {
        const uint32_t* Qs = fsm + KSTG;
#pragma unroll
        for (int c = 0; c < 4; ++c) {
            qf[c][0] = Qs[(qrow + g)     * KW2 + 8 * c + tg];
            qf[c][1] = Qs[(qrow + g + 8) * KW2 + 8 * c + tg];
            qf[c][2] = Qs[(qrow + g)     * KW2 + 8 * c + tg + 4];
            qf[c][3] = Qs[(qrow + g + 8) * KW2 + 8 * c + tg + 4];
        }
    }
    __syncthreads();

    if (qi >= 1) {
        ISSUE_KV(1, 1);
        cpa_commit();
    }

    float m1 = -INFINITY, m2 = -INFINITY, l1 = 0.0f, l2 = 0.0f;
    float oacc[8][4];
#pragma unroll
    for (int nt = 0; nt < 8; ++nt)
#pragma unroll
        for (int c = 0; c < 4; ++c) oacc[nt][c] = 0.0f;

    for (int j = 0; j <= qi; ++j) {
        if (j < qi) cpa_wait<1>(); else cpa_wait<0>();
        __syncthreads();

        const uint32_t* Ks = fsm + (j & 1) * KSTG;
        const uint32_t* Vs = fsm + 2 * KSTG + (j & 1) * VSTG;
        const int k0 = j * 64;

        float sacc[8][4];
#pragma unroll
        for (int nt = 0; nt < 8; ++nt)
#pragma unroll
            for (int c = 0; c < 4; ++c) sacc[nt][c] = 0.0f;

#pragma unroll
        for (int nt = 0; nt < 8; ++nt) {
#pragma unroll
            for (int c = 0; c < 4; ++c) {
                uint32_t bf[2];
                bf[0] = Ks[(nt * 8 + g) * KW2 + 8 * c + tg];
                bf[1] = Ks[(nt * 8 + g) * KW2 + 8 * c + tg + 4];
                mma_f16(sacc[nt], qf[c], bf);
            }
        }

        if (j == qi) {
            int r1 = q0 + qrow + g, r2 = r1 + 8;
#pragma unroll
            for (int nt = 0; nt < 8; ++nt) {
                int c0 = k0 + nt * 8 + tg * 2;
                if (c0     > r1) sacc[nt][0] = -INFINITY;
                if (c0 + 1 > r1) sacc[nt][1] = -INFINITY;
                if (c0     > r2) sacc[nt][2] = -INFINITY;
                if (c0 + 1 > r2) sacc[nt][3] = -INFINITY;
            }
        }

        float a1 = -INFINITY, a2 = -INFINITY;
#pragma unroll
        for (int nt = 0; nt < 8; ++nt) {
            a1 = fmaxf(a1, fmaxf(sacc[nt][0], sacc[nt][1]));
            a2 = fmaxf(a2, fmaxf(sacc[nt][2], sacc[nt][3]));
        }
        a1 = fmaxf(a1, __shfl_xor_sync(0xffffffff, a1, 1));
        a1 = fmaxf(a1, __shfl_xor_sync(0xffffffff, a1, 2));
        a2 = fmaxf(a2, __shfl_xor_sync(0xffffffff, a2, 1));
        a2 = fmaxf(a2, __shfl_xor_sync(0xffffffff, a2, 2));

        float mn1 = fmaxf(m1, a1), mn2 = fmaxf(m2, a2);
        float al1 = ex2f(m1 - mn1), al2 = ex2f(m2 - mn2);

        float s1 = 0.0f, s2 = 0.0f;
#pragma unroll
        for (int nt = 0; nt < 8; ++nt) {
            sacc[nt][0] = ex2f(sacc[nt][0] - mn1);
            sacc[nt][1] = ex2f(sacc[nt][1] - mn1);
            sacc[nt][2] = ex2f(sacc[nt][2] - mn2);
            sacc[nt][3] = ex2f(sacc[nt][3] - mn2);
            s1 += sacc[nt][0] + sacc[nt][1];
            s2 += sacc[nt][2] + sacc[nt][3];
        }
        s1 += __shfl_xor_sync(0xffffffff, s1, 1);
        s1 += __shfl_xor_sync(0xffffffff, s1, 2);
        s2 += __shfl_xor_sync(0xffffffff, s2, 1);
        s2 += __shfl_xor_sync(0xffffffff, s2, 2);

        l1 = l1 * al1 + s1;
        l2 = l2 * al2 + s2;
        m1 = mn1;
        m2 = mn2;

#pragma unroll
        for (int nt = 0; nt < 8; ++nt) {
            oacc[nt][0] *= al1; oacc[nt][1] *= al1;
            oacc[nt][2] *= al2; oacc[nt][3] *= al2;
        }

#pragma unroll
        for (int c = 0; c < 4; ++c) {
            uint32_t af[4];
            af[0] = packh2(sacc[2 * c][0],     sacc[2 * c][1]);
            af[1] = packh2(sacc[2 * c][2],     sacc[2 * c][3]);
            af[2] = packh2(sacc[2 * c + 1][0], sacc[2 * c + 1][1]);
            af[3] = packh2(sacc[2 * c + 1][2], sacc[2 * c + 1][3]);
#pragma unroll
            for (int nt = 0; nt < 8; ++nt) {
                uint32_t bf[2];
                bf[0] = Vs[(8 * c + tg)     * VW2 + nt * 8 + g];
                bf[1] = Vs[(8 * c + tg + 4) * VW2 + nt * 8 + g];
                mma_f16(oacc[nt], af, bf);
            }
        }

        __syncthreads();
        if (j + 2 <= qi) {
            ISSUE_KV(j + 2, j & 1);
            cpa_commit();
        }
    }

    float i1 = 1.0f / l1, i2 = 1.0f / l2;
    int r1 = q0 + qrow + g, r2 = r1 + 8;
#pragma unroll
    for (int nt = 0; nt < 8; ++nt) {
        int col = h * D_ + nt * 8 + tg * 2;
        __half2 lo = __floats2half2_rn(oacc[nt][0] * i1, oacc[nt][1] * i1);
        __half2 hi = __floats2half2_rn(oacc[nt][2] * i2, oacc[nt][3] * i2);
        *(__half2*)(O + (size_t)(bT + r1) * C_ + col) = lo;
        *(__half2*)(O + (size_t)(bT + r2) * C_ + col) = hi;
    }
}

// ---------------------------------------------------------------------------
extern "C" void kernel_launch(void* const* d_in, const int* in_sizes, int n_in,
                              void* d_out, int out_size) {
    const float* x  = (const float*)d_in[0];
    const float* Wq = (const float*)d_in[1];
    const float* Wk = (const float*)d_in[2];
    const float* Wv = (const float*)d_in[3];
    const float* Wp = (const float*)d_in[4];
    float* out = (float*)d_out;

    __half *qh, *kh, *vp, *xh, *wqkvh, *wph, *atth;
    cudaGetSymbolAddress((void**)&qh,    g_qh);
    cudaGetSymbolAddress((void**)&kh,    g_kh);
    cudaGetSymbolAddress((void**)&vp,    g_vp);
    cudaGetSymbolAddress((void**)&xh,    g_xh);
    cudaGetSymbolAddress((void**)&wqkvh, g_wqkvh);
    cudaGetSymbolAddress((void**)&wph,   g_wph);
    cudaGetSymbolAddress((void**)&atth,  g_atth);

    cudaFuncSetAttribute(gemm_hp<1>,
                         cudaFuncAttributeMaxDynamicSharedMemorySize, SMEM_G);
    cudaFuncSetAttribute(gemm_hp<0>,
                         cudaFuncAttributeMaxDynamicSharedMemorySize, SMEM_G);
    cudaFuncSetAttribute(flash_tc,
                         cudaFuncAttributeMaxDynamicSharedMemorySize, SMEM_F);

    // 1. fp16 pre-conversion + weight interleave + rope table
    cvt_pack<<<(M_TOK * C_ / 4 + 255) / 256, 256>>>(x, Wq, Wk, Wv, Wp);

    // 2. fused QKV projection + RoPE epilogue (q/k fp16 rotated, v packed)
    gemm_hp<1><<<dim3(NQKV / 128, M_TOK / 128), 256, SMEM_G>>>(
        xh, wqkvh, nullptr, M_TOK, NQKV, C_);

    // 3. causal flash attention with GQA (fp16 mma)
    flash_tc<<<dim3(T_ / 64, B_ * H_), 128, SMEM_F>>>(qh, kh, vp, atth);

    // 4. output projection (fp16 mma)
    gemm_hp<0><<<dim3(C_ / 128, M_TOK / 128), 256, SMEM_G>>>(
        atth, wph, out, M_TOK, C_, C_);
}